// round 7
// baseline (speedup 1.0000x reference)
#include <cuda_runtime.h>
#include <cuda_bf16.h>
#include <cstdio>

#define BB 2
#define TT 2048
#define NH 12
#define DH 64
#define DM 768
#define NQKV (3*DM)
#define MROWS (BB*TT)   // 4096
#define OUT_ELEMS ((size_t)MROWS*DM)

// Scratch (allocation-free)
__device__ __align__(16) float g_q[(size_t)BB*NH*TT*DH];
__device__ __align__(16) float g_k[(size_t)BB*NH*TT*DH];
__device__ __align__(16) float g_v[(size_t)BB*NH*TT*DH];
__device__ __align__(16) float g_y[(size_t)MROWS*DM];

// ---------------- Tiled SGEMM ----------------------------------------------------
#define GBM 64
#define GBN 64
#define GBK 16

// MODE 0: C = A*B + bias            (A passed from host)
// MODE 1: QKV scatter epilogue      (A passed from host, writes g_q/g_k/g_v)
// MODE 2: C = g_y*B + bias          (A bound IN DEVICE CODE -- never pass a
//                                    __device__ symbol from host: on GB300's
//                                    ATS it silently reads host zeros!)
template <int MODE>
__global__ __launch_bounds__(256) void gemm_kernel(
    const float* __restrict__ A_, const float* __restrict__ Bw,
    const float* __restrict__ bias, float* __restrict__ Cout,
    int N, int K)
{
    const float* __restrict__ A = (MODE == 2) ? (const float*)g_y : A_;

    __shared__ float As[GBM][GBK + 1];
    __shared__ float Bs[GBK][GBN];

    const int tid = threadIdx.x;
    const int tx = tid & 15;
    const int ty = tid >> 4;
    const int bm = blockIdx.y * GBM;
    const int bn = blockIdx.x * GBN;

    float acc[4][4];
#pragma unroll
    for (int i = 0; i < 4; i++)
#pragma unroll
        for (int j = 0; j < 4; j++) acc[i][j] = 0.f;

    const int a_row = tid >> 2;
    const int a_f4  = (tid & 3) * 4;
    const int b_row = tid >> 4;
    const int b_n4  = (tid & 15) * 4;

    for (int k0 = 0; k0 < K; k0 += GBK) {
        float4 va = *(const float4*)(A + (size_t)(bm + a_row) * K + k0 + a_f4);
        As[a_row][a_f4 + 0] = va.x;
        As[a_row][a_f4 + 1] = va.y;
        As[a_row][a_f4 + 2] = va.z;
        As[a_row][a_f4 + 3] = va.w;
        *(float4*)&Bs[b_row][b_n4] =
            *(const float4*)(Bw + (size_t)(k0 + b_row) * N + bn + b_n4);
        __syncthreads();

#pragma unroll
        for (int kk = 0; kk < GBK; kk++) {
            float a0 = As[ty * 4 + 0][kk];
            float a1 = As[ty * 4 + 1][kk];
            float a2 = As[ty * 4 + 2][kk];
            float a3 = As[ty * 4 + 3][kk];
            float4 b4 = *(const float4*)&Bs[kk][tx * 4];
            acc[0][0] += a0 * b4.x; acc[0][1] += a0 * b4.y; acc[0][2] += a0 * b4.z; acc[0][3] += a0 * b4.w;
            acc[1][0] += a1 * b4.x; acc[1][1] += a1 * b4.y; acc[1][2] += a1 * b4.z; acc[1][3] += a1 * b4.w;
            acc[2][0] += a2 * b4.x; acc[2][1] += a2 * b4.y; acc[2][2] += a2 * b4.z; acc[2][3] += a2 * b4.w;
            acc[3][0] += a3 * b4.x; acc[3][1] += a3 * b4.y; acc[3][2] += a3 * b4.z; acc[3][3] += a3 * b4.w;
        }
        __syncthreads();
    }

#pragma unroll
    for (int i = 0; i < 4; i++) {
        int m = bm + ty * 4 + i;
#pragma unroll
        for (int j = 0; j < 4; j++) {
            int n = bn + tx * 4 + j;
            float c = acc[i][j] + bias[n];
            if (MODE != 1) {
                Cout[(size_t)m * N + n] = c;
            } else {
                int which = n / DM;
                int hd = n % DM;
                int h = hd / DH;
                int d = hd % DH;
                int b = m / TT;
                int t = m % TT;
                float* dst = (which == 0) ? g_q : (which == 1) ? g_k : g_v;
                dst[(((size_t)(b * NH + h)) * TT + t) * DH + d] = c;
            }
        }
    }
}

// ---------------- Flash-style causal attention -----------------------------------
#define ABM 64
#define ABN 32

__global__ __launch_bounds__(64) void attn_kernel()
{
    const int bh = blockIdx.y;
    const int qt = blockIdx.x;
    const int tid = threadIdx.x;
    const int qi = qt * ABM + tid;
    const float scale = 0.125f;

    const size_t base = (size_t)bh * TT * DH;

    float q[DH];
    {
        const float* qp = g_q + base + (size_t)qi * DH;
#pragma unroll
        for (int d = 0; d < DH; d++) q[d] = qp[d] * scale;
    }

    float o[DH];
#pragma unroll
    for (int d = 0; d < DH; d++) o[d] = 0.f;
    float mrun = -1e30f, lrun = 0.f;

    __shared__ float ks[ABN][DH];
    __shared__ float vs[ABN][DH];
    __shared__ float sc[ABN][ABM];

    const int ntiles = 2 * qt + 2;

    for (int kt = 0; kt < ntiles; kt++) {
        __syncthreads();
        const float* kp = g_k + base + (size_t)(kt * ABN) * DH + tid;
        const float* vp = g_v + base + (size_t)(kt * ABN) * DH + tid;
#pragma unroll 8
        for (int r = 0; r < ABN; r++) {
            ks[r][tid] = kp[r * DH];
            vs[r][tid] = vp[r * DH];
        }
        __syncthreads();

        int rem = qi - kt * ABN + 1;
        int jmax = rem < ABN ? rem : ABN;
        if (jmax > 0) {
            float tmax = -1e30f;
            for (int j = 0; j < jmax; j++) {
                const float4* kr = (const float4*)ks[j];
                float s0 = 0.f, s1 = 0.f, s2 = 0.f, s3 = 0.f;
#pragma unroll
                for (int d4 = 0; d4 < 16; d4 += 4) {
                    float4 k0 = kr[d4 + 0], k1 = kr[d4 + 1], k2 = kr[d4 + 2], k3 = kr[d4 + 3];
                    s0 += q[(d4+0)*4+0]*k0.x + q[(d4+0)*4+1]*k0.y + q[(d4+0)*4+2]*k0.z + q[(d4+0)*4+3]*k0.w;
                    s1 += q[(d4+1)*4+0]*k1.x + q[(d4+1)*4+1]*k1.y + q[(d4+1)*4+2]*k1.z + q[(d4+1)*4+3]*k1.w;
                    s2 += q[(d4+2)*4+0]*k2.x + q[(d4+2)*4+1]*k2.y + q[(d4+2)*4+2]*k2.z + q[(d4+2)*4+3]*k2.w;
                    s3 += q[(d4+3)*4+0]*k3.x + q[(d4+3)*4+1]*k3.y + q[(d4+3)*4+2]*k3.z + q[(d4+3)*4+3]*k3.w;
                }
                float s = (s0 + s1) + (s2 + s3);
                sc[j][tid] = s;
                tmax = fmaxf(tmax, s);
            }
            float newm = fmaxf(mrun, tmax);
            float f = __expf(mrun - newm);
            lrun *= f;
#pragma unroll
            for (int d = 0; d < DH; d++) o[d] *= f;
            for (int j = 0; j < jmax; j++) {
                float p = __expf(sc[j][tid] - newm);
                lrun += p;
                const float4* vr = (const float4*)vs[j];
#pragma unroll
                for (int d4 = 0; d4 < 16; d4++) {
                    float4 v4 = vr[d4];
                    o[d4*4+0] += p * v4.x;
                    o[d4*4+1] += p * v4.y;
                    o[d4*4+2] += p * v4.z;
                    o[d4*4+3] += p * v4.w;
                }
            }
            mrun = newm;
        }
    }

    const float inv = 1.0f / lrun;
    const int b = bh / NH;
    const int h = bh % NH;
    float* yp = g_y + ((size_t)(b * TT + qi)) * DM + h * DH;
#pragma unroll
    for (int d = 0; d < DH; d++) yp[d] = o[d] * inv;
}

// ---------------- exact-recompute tripwire (kept one more round) ------------------
__global__ void check_kernel(const float* x, const float* wa, const float* ba,
                             const float* wp, const float* bp, float* out)
{
    __shared__ float v0[DM];
    __shared__ int flag;
    __shared__ int errmask;
    const int c = threadIdx.x;   // 768 threads
    if (c == 0) { errmask = 0; flag = 0; }
    __syncthreads();

    // v0[c] = x[0,:] . w_attn[:, 1536+c] + b_attn[1536+c]
    float s = ba[1536 + c];
    for (int k = 0; k < DM; k++)
        s += x[k] * wa[(size_t)k * NQKV + 1536 + c];
    v0[c] = s;
    __syncthreads();

    float tol = 1e-2f * (1.f + fabsf(s));
    float gv = g_v[(size_t)(c / DH) * TT * DH + (c % DH)];
    if (fabsf(gv - s) > tol) atomicOr(&errmask, 1);
    if (fabsf(g_y[c] - s) > tol) atomicOr(&errmask, 2);
    float s3 = bp[c];
    for (int k = 0; k < DM; k++)
        s3 += v0[k] * wp[(size_t)k * DM + c];
    if (fabsf(out[c] - s3) > 1e-2f * (1.f + fabsf(s3))) atomicOr(&errmask, 4);
    __syncthreads();

    if (c == 0) {
        if      (errmask & 1) flag = 5;
        else if (errmask & 2) flag = 6;
        else if (errmask & 4) flag = 7;
    }
    __syncthreads();
    int f = flag;
    if (f != 0) {
        float sent = __powf(10.f, (float)(f + 1));
        for (size_t i = c; i < OUT_ELEMS; i += blockDim.x) out[i] = sent;
    }
}

// ---------------- launch -----------------------------------------------------------
extern "C" void kernel_launch(void* const* d_in, const int* in_sizes, int n_in,
                              void* d_out, int out_size)
{
    const float *x = nullptr, *wa = nullptr, *ba = nullptr, *wp = nullptr, *bp = nullptr;
    for (int divi = 0; divi < 2; divi++) {
        long long div = (divi == 0) ? 1 : 4;
        const float *tx=nullptr,*twa=nullptr,*tba=nullptr,*twp=nullptr,*tbp=nullptr;
        for (int i = 0; i < n_in; i++) {
            long long s = (long long)in_sizes[i] / div;
            if      (s == 3145728) tx  = (const float*)d_in[i];
            else if (s == 1769472) twa = (const float*)d_in[i];
            else if (s == 589824)  twp = (const float*)d_in[i];
            else if (s == 2304)    tba = (const float*)d_in[i];
            else if (s == 768)     tbp = (const float*)d_in[i];
        }
        if (tx && twa && tba && twp && tbp) { x=tx; wa=twa; ba=tba; wp=twp; bp=tbp; break; }
    }
    if (!(x && wa && ba && wp && bp)) {
        printf("DIAG size contract mismatch: n_in=%d sizes:", n_in);
        for (int i = 0; i < n_in && i < 16; i++) printf(" %d", in_sizes[i]);
        printf("\n"); fflush(stdout);
        return;
    }

    float* out = (float*)d_out;

    // 1) QKV projection -> q/k/v [B,H,T,D]
    {
        dim3 grid(NQKV / GBN, MROWS / GBM);
        gemm_kernel<1><<<grid, 256>>>(x, wa, ba, nullptr, NQKV, DM);
    }
    // 2) causal attention -> g_y [B,T,C]
    {
        dim3 grid(TT / ABM, BB * NH);
        attn_kernel<<<grid, 64>>>();
    }
    // 3) output projection (A = g_y bound in device code, MODE 2)
    {
        dim3 grid(DM / GBN, MROWS / GBM);
        gemm_kernel<2><<<grid, 256>>>(nullptr, wp, bp, out, DM, DM);
    }
    // 4) tripwire
    check_kernel<<<1, DM>>>(x, wa, ba, wp, bp, out);
}

// round 8
// speedup vs baseline: 1.2424x; 1.2424x over previous
#include <cuda_runtime.h>
#include <cuda_bf16.h>
#include <mma.h>
#include <cstdio>

using namespace nvcuda;

#define BB 2
#define TT 2048
#define NH 12
#define DH 64
#define DM 768
#define NQKV (3*DM)
#define MROWS (BB*TT)   // 4096

// Scratch (allocation-free). NOTE: never pass these symbols from host code —
// GB300 ATS silently resolves the host shadow address (reads zeros).
__device__ __align__(16) float g_q[(size_t)BB*NH*TT*DH];
__device__ __align__(16) float g_k[(size_t)BB*NH*TT*DH];
__device__ __align__(16) float g_v[(size_t)BB*NH*TT*DH];
__device__ __align__(16) float g_y[(size_t)MROWS*DM];

// ---------------- tf32 tensor-core GEMM --------------------------------------------
// C[M,N] = A[M,K] * B[K,N] + bias, tiles: BM=128, BN=64, BK=16, 256 threads (8 warps)
// warp grid 4(m) x 2(n), warp tile 32x32 = 2x2 wmma(16x16x8) tiles.
// MODE 1: A from param (x), epilogue scatters into g_q/g_k/g_v [B,H,T,D]
// MODE 2: A = g_y (bound in device code), plain store + bias
#define BM 128
#define BN 64
#define BK 16
#define AKP 20   // As leading dim (pad, mult of 4)
#define BNP 72   // Bs leading dim
#define CNP 68   // Cs leading dim

template <int MODE>
__global__ __launch_bounds__(256) void gemm_tc(
    const float* __restrict__ A_, const float* __restrict__ Bw,
    const float* __restrict__ bias, float* __restrict__ Cout,
    int N, int K)
{
    const float* __restrict__ A = (MODE == 2) ? (const float*)g_y : A_;

    __shared__ union {
        struct {
            float As[BM][AKP];
            float Bs[BK][BNP];
        } ld;
        float Cs[BM][CNP];
    } sm;

    const int tid  = threadIdx.x;
    const int warp = tid >> 5;
    const int wm   = warp & 3;        // 0..3  -> m offset wm*32
    const int wn   = warp >> 2;       // 0..1  -> n offset wn*32
    const int bm   = blockIdx.y * BM;
    const int bn   = blockIdx.x * BN;

    wmma::fragment<wmma::accumulator, 16, 16, 8, float> acc[2][2];
#pragma unroll
    for (int i = 0; i < 2; i++)
#pragma unroll
        for (int j = 0; j < 2; j++) wmma::fill_fragment(acc[i][j], 0.f);

    for (int k0 = 0; k0 < K; k0 += BK) {
        // Load A tile 128x16: 512 float4 / 256 threads = 2 each
#pragma unroll
        for (int i = 0; i < 2; i++) {
            int idx = tid + i * 256;
            int r = idx >> 2;
            int c4 = (idx & 3) << 2;
            float4 v = *(const float4*)(A + (size_t)(bm + r) * K + k0 + c4);
            *(float4*)&sm.ld.As[r][c4] = v;
        }
        // Load B tile 16x64: 256 float4 / 256 threads = 1 each
        {
            int r = tid >> 4;
            int c4 = (tid & 15) << 2;
            float4 v = *(const float4*)(Bw + (size_t)(k0 + r) * N + bn + c4);
            *(float4*)&sm.ld.Bs[r][c4] = v;
        }
        __syncthreads();

#pragma unroll
        for (int ks = 0; ks < BK; ks += 8) {
            wmma::fragment<wmma::matrix_a, 16, 16, 8, wmma::precision::tf32, wmma::row_major> af[2];
            wmma::fragment<wmma::matrix_b, 16, 16, 8, wmma::precision::tf32, wmma::row_major> bf[2];
#pragma unroll
            for (int i = 0; i < 2; i++) {
                wmma::load_matrix_sync(af[i], &sm.ld.As[wm * 32 + i * 16][ks], AKP);
#pragma unroll
                for (int e = 0; e < af[i].num_elements; e++)
                    af[i].x[e] = wmma::__float_to_tf32(af[i].x[e]);
            }
#pragma unroll
            for (int j = 0; j < 2; j++) {
                wmma::load_matrix_sync(bf[j], &sm.ld.Bs[ks][wn * 32 + j * 16], BNP);
#pragma unroll
                for (int e = 0; e < bf[j].num_elements; e++)
                    bf[j].x[e] = wmma::__float_to_tf32(bf[j].x[e]);
            }
#pragma unroll
            for (int i = 0; i < 2; i++)
#pragma unroll
                for (int j = 0; j < 2; j++)
                    wmma::mma_sync(acc[i][j], af[i], bf[j], acc[i][j]);
        }
        __syncthreads();
    }

    // Epilogue via smem (union reuse)
#pragma unroll
    for (int i = 0; i < 2; i++)
#pragma unroll
        for (int j = 0; j < 2; j++)
            wmma::store_matrix_sync(&sm.Cs[wm * 32 + i * 16][wn * 32 + j * 16],
                                    acc[i][j], CNP, wmma::mem_row_major);
    __syncthreads();

    // 128x64 outputs / 256 threads = 32 each (row-chunks of 8 rows x 64 cols)
#pragma unroll
    for (int it = 0; it < 32; it++) {
        int idx = tid + it * 256;          // 0..8191
        int r = idx >> 6;                  // 0..127
        int n_loc = idx & 63;
        int m = bm + r;
        int n = bn + n_loc;
        float c = sm.Cs[r][n_loc] + bias[n];
        if (MODE != 1) {
            Cout[(size_t)m * N + n] = c;
        } else {
            int which = n / DM;
            int hd = n % DM;
            int h = hd / DH;
            int d = hd % DH;
            int b = m / TT;
            int t = m % TT;
            float* dst = (which == 0) ? g_q : (which == 1) ? g_k : g_v;
            dst[(((size_t)(b * NH + h)) * TT + t) * DH + d] = c;
        }
    }
}

// ---------------- Flash-style causal attention (fp32, unchanged) -------------------
#define ABM 64
#define ABN 32

__global__ __launch_bounds__(64) void attn_kernel()
{
    const int bh = blockIdx.y;
    const int qt = blockIdx.x;
    const int tid = threadIdx.x;
    const int qi = qt * ABM + tid;
    const float scale = 0.125f;

    const size_t base = (size_t)bh * TT * DH;

    float q[DH];
    {
        const float* qp = g_q + base + (size_t)qi * DH;
#pragma unroll
        for (int d = 0; d < DH; d++) q[d] = qp[d] * scale;
    }

    float o[DH];
#pragma unroll
    for (int d = 0; d < DH; d++) o[d] = 0.f;
    float mrun = -1e30f, lrun = 0.f;

    __shared__ float ks[ABN][DH];
    __shared__ float vs[ABN][DH];
    __shared__ float sc[ABN][ABM];

    const int ntiles = 2 * qt + 2;

    for (int kt = 0; kt < ntiles; kt++) {
        __syncthreads();
        const float* kp = g_k + base + (size_t)(kt * ABN) * DH + tid;
        const float* vp = g_v + base + (size_t)(kt * ABN) * DH + tid;
#pragma unroll 8
        for (int r = 0; r < ABN; r++) {
            ks[r][tid] = kp[r * DH];
            vs[r][tid] = vp[r * DH];
        }
        __syncthreads();

        int rem = qi - kt * ABN + 1;
        int jmax = rem < ABN ? rem : ABN;
        if (jmax > 0) {
            float tmax = -1e30f;
            for (int j = 0; j < jmax; j++) {
                const float4* kr = (const float4*)ks[j];
                float s0 = 0.f, s1 = 0.f, s2 = 0.f, s3 = 0.f;
#pragma unroll
                for (int d4 = 0; d4 < 16; d4 += 4) {
                    float4 k0 = kr[d4 + 0], k1 = kr[d4 + 1], k2 = kr[d4 + 2], k3 = kr[d4 + 3];
                    s0 += q[(d4+0)*4+0]*k0.x + q[(d4+0)*4+1]*k0.y + q[(d4+0)*4+2]*k0.z + q[(d4+0)*4+3]*k0.w;
                    s1 += q[(d4+1)*4+0]*k1.x + q[(d4+1)*4+1]*k1.y + q[(d4+1)*4+2]*k1.z + q[(d4+1)*4+3]*k1.w;
                    s2 += q[(d4+2)*4+0]*k2.x + q[(d4+2)*4+1]*k2.y + q[(d4+2)*4+2]*k2.z + q[(d4+2)*4+3]*k2.w;
                    s3 += q[(d4+3)*4+0]*k3.x + q[(d4+3)*4+1]*k3.y + q[(d4+3)*4+2]*k3.z + q[(d4+3)*4+3]*k3.w;
                }
                float s = (s0 + s1) + (s2 + s3);
                sc[j][tid] = s;
                tmax = fmaxf(tmax, s);
            }
            float newm = fmaxf(mrun, tmax);
            float f = __expf(mrun - newm);
            lrun *= f;
#pragma unroll
            for (int d = 0; d < DH; d++) o[d] *= f;
            for (int j = 0; j < jmax; j++) {
                float p = __expf(sc[j][tid] - newm);
                lrun += p;
                const float4* vr = (const float4*)vs[j];
#pragma unroll
                for (int d4 = 0; d4 < 16; d4++) {
                    float4 v4 = vr[d4];
                    o[d4*4+0] += p * v4.x;
                    o[d4*4+1] += p * v4.y;
                    o[d4*4+2] += p * v4.z;
                    o[d4*4+3] += p * v4.w;
                }
            }
            mrun = newm;
        }
    }

    const float inv = 1.0f / lrun;
    const int b = bh / NH;
    const int h = bh % NH;
    float* yp = g_y + ((size_t)(b * TT + qi)) * DM + h * DH;
#pragma unroll
    for (int d = 0; d < DH; d++) yp[d] = o[d] * inv;
}

// ---------------- launch -----------------------------------------------------------
extern "C" void kernel_launch(void* const* d_in, const int* in_sizes, int n_in,
                              void* d_out, int out_size)
{
    const float *x = nullptr, *wa = nullptr, *ba = nullptr, *wp = nullptr, *bp = nullptr;
    for (int divi = 0; divi < 2; divi++) {
        long long div = (divi == 0) ? 1 : 4;
        const float *tx=nullptr,*twa=nullptr,*tba=nullptr,*twp=nullptr,*tbp=nullptr;
        for (int i = 0; i < n_in; i++) {
            long long s = (long long)in_sizes[i] / div;
            if      (s == 3145728) tx  = (const float*)d_in[i];
            else if (s == 1769472) twa = (const float*)d_in[i];
            else if (s == 589824)  twp = (const float*)d_in[i];
            else if (s == 2304)    tba = (const float*)d_in[i];
            else if (s == 768)     tbp = (const float*)d_in[i];
        }
        if (tx && twa && tba && twp && tbp) { x=tx; wa=twa; ba=tba; wp=twp; bp=tbp; break; }
    }
    if (!(x && wa && ba && wp && bp)) return;

    float* out = (float*)d_out;

    // 1) QKV projection (tf32 TC) -> q/k/v [B,H,T,D]
    {
        dim3 grid(NQKV / BN, MROWS / BM);   // (36, 32)
        gemm_tc<1><<<grid, 256>>>(x, wa, ba, nullptr, NQKV, DM);
    }
    // 2) causal attention (fp32) -> g_y [B,T,C]
    {
        dim3 grid(TT / ABM, BB * NH);       // (32, 24)
        attn_kernel<<<grid, 64>>>();
    }
    // 3) output projection (tf32 TC, A=g_y bound in device code)
    {
        dim3 grid(DM / BN, MROWS / BM);     // (12, 32)
        gemm_tc<2><<<grid, 256>>>(nullptr, wp, bp, out, DM, DM);
    }
}

// round 9
// speedup vs baseline: 1.7948x; 1.4445x over previous
#include <cuda_runtime.h>
#include <cuda_bf16.h>
#include <mma.h>
#include <cstdio>

using namespace nvcuda;

#define BB 2
#define TT 2048
#define NH 12
#define DH 64
#define DM 768
#define NQKV (3*DM)
#define MROWS (BB*TT)   // 4096

// Scratch (allocation-free). NOTE: never pass these symbols from host code —
// GB300 ATS silently resolves the host shadow address (reads zeros).
__device__ __align__(16) float g_q[(size_t)BB*NH*TT*DH];
__device__ __align__(16) float g_k[(size_t)BB*NH*TT*DH];
__device__ __align__(16) float g_v[(size_t)BB*NH*TT*DH];
__device__ __align__(16) float g_y[(size_t)MROWS*DM];

// ---------------- tf32 tensor-core GEMM (unchanged from R8) ------------------------
#define BM 128
#define BN 64
#define BK 16
#define AKP 20
#define BNP 72
#define CNP 68

template <int MODE>
__global__ __launch_bounds__(256) void gemm_tc(
    const float* __restrict__ A_, const float* __restrict__ Bw,
    const float* __restrict__ bias, float* __restrict__ Cout,
    int N, int K)
{
    const float* __restrict__ A = (MODE == 2) ? (const float*)g_y : A_;

    __shared__ union {
        struct { float As[BM][AKP]; float Bs[BK][BNP]; } ld;
        float Cs[BM][CNP];
    } sm;

    const int tid  = threadIdx.x;
    const int warp = tid >> 5;
    const int wm   = warp & 3;
    const int wn   = warp >> 2;
    const int bm   = blockIdx.y * BM;
    const int bn   = blockIdx.x * BN;

    wmma::fragment<wmma::accumulator, 16, 16, 8, float> acc[2][2];
#pragma unroll
    for (int i = 0; i < 2; i++)
#pragma unroll
        for (int j = 0; j < 2; j++) wmma::fill_fragment(acc[i][j], 0.f);

    for (int k0 = 0; k0 < K; k0 += BK) {
#pragma unroll
        for (int i = 0; i < 2; i++) {
            int idx = tid + i * 256;
            int r = idx >> 2;
            int c4 = (idx & 3) << 2;
            float4 v = *(const float4*)(A + (size_t)(bm + r) * K + k0 + c4);
            *(float4*)&sm.ld.As[r][c4] = v;
        }
        {
            int r = tid >> 4;
            int c4 = (tid & 15) << 2;
            float4 v = *(const float4*)(Bw + (size_t)(k0 + r) * N + bn + c4);
            *(float4*)&sm.ld.Bs[r][c4] = v;
        }
        __syncthreads();

#pragma unroll
        for (int ks = 0; ks < BK; ks += 8) {
            wmma::fragment<wmma::matrix_a, 16, 16, 8, wmma::precision::tf32, wmma::row_major> af[2];
            wmma::fragment<wmma::matrix_b, 16, 16, 8, wmma::precision::tf32, wmma::row_major> bf[2];
#pragma unroll
            for (int i = 0; i < 2; i++) {
                wmma::load_matrix_sync(af[i], &sm.ld.As[wm * 32 + i * 16][ks], AKP);
#pragma unroll
                for (int e = 0; e < af[i].num_elements; e++)
                    af[i].x[e] = wmma::__float_to_tf32(af[i].x[e]);
            }
#pragma unroll
            for (int j = 0; j < 2; j++) {
                wmma::load_matrix_sync(bf[j], &sm.ld.Bs[ks][wn * 32 + j * 16], BNP);
#pragma unroll
                for (int e = 0; e < bf[j].num_elements; e++)
                    bf[j].x[e] = wmma::__float_to_tf32(bf[j].x[e]);
            }
#pragma unroll
            for (int i = 0; i < 2; i++)
#pragma unroll
                for (int j = 0; j < 2; j++)
                    wmma::mma_sync(acc[i][j], af[i], bf[j], acc[i][j]);
        }
        __syncthreads();
    }

#pragma unroll
    for (int i = 0; i < 2; i++)
#pragma unroll
        for (int j = 0; j < 2; j++)
            wmma::store_matrix_sync(&sm.Cs[wm * 32 + i * 16][wn * 32 + j * 16],
                                    acc[i][j], CNP, wmma::mem_row_major);
    __syncthreads();

#pragma unroll
    for (int it = 0; it < 32; it++) {
        int idx = tid + it * 256;
        int r = idx >> 6;
        int n_loc = idx & 63;
        int m = bm + r;
        int n = bn + n_loc;
        float c = sm.Cs[r][n_loc] + bias[n];
        if (MODE != 1) {
            Cout[(size_t)m * N + n] = c;
        } else {
            int which = n / DM;
            int hd = n % DM;
            int h = hd / DH;
            int d = hd % DH;
            int b = m / TT;
            int t = m % TT;
            float* dst = (which == 0) ? g_q : (which == 1) ? g_k : g_v;
            dst[(((size_t)(b * NH + h)) * TT + t) * DH + d] = c;
        }
    }
}

// ---------------- Tensor-core flash attention --------------------------------------
// Block = (bh, 64-query tile), 128 threads (4 warps).
// S = Q*K^T via 3-term bf16 wmma (fp32-accurate), softmax fp32 with FMA-pipe exp2,
// P*V via tf32 wmma. O kept in registers (thread-pair per row), PV staged via smem.
#define LOG2E 1.4426950408889634f

__device__ __forceinline__ float fexp2(float t)  // t <= 0; returns 2^t
{
    t = fmaxf(t, -126.f);
    float fl = floorf(t);
    float f = t - fl;                       // [0,1)
    float x = f * 0.69314718056f;
    float p = 1.f + x*(1.f + x*(0.5f + x*(0.16666667f + x*(0.041666667f
              + x*(0.0083333333f + x*0.0013888889f)))));
    return __int_as_float(__float_as_int(p) + ((int)fl << 23));
}

// dynamic smem layout (bytes)
#define OFF_QH 0
#define OFF_QL 9216
#define OFF_KH 18432
#define OFF_KL 27648
#define OFF_VS 36864
#define OFF_PS 54272
#define OFF_PV 71680
#define OFF_M  89088
#define OFF_L  89344
#define ATT_SMEM 89600
#define LDB 72   // bf16 tiles leading dim
#define LDF 68   // fp32 tiles leading dim

__global__ __launch_bounds__(128) void attn_tc()
{
    extern __shared__ char smraw[];
    __nv_bfloat16* Qh = (__nv_bfloat16*)(smraw + OFF_QH);
    __nv_bfloat16* Ql = (__nv_bfloat16*)(smraw + OFF_QL);
    __nv_bfloat16* Kh = (__nv_bfloat16*)(smraw + OFF_KH);
    __nv_bfloat16* Kl = (__nv_bfloat16*)(smraw + OFF_KL);
    float* Vs = (float*)(smraw + OFF_VS);
    float* Ps = (float*)(smraw + OFF_PS);
    float* PV = (float*)(smraw + OFF_PV);
    float* mrow = (float*)(smraw + OFF_M);
    float* lrow = (float*)(smraw + OFF_L);

    const int bh  = blockIdx.y;
    const int qt  = gridDim.x - 1 - blockIdx.x;  // heavy tiles scheduled first
    const int tid = threadIdx.x;
    const int warp = tid >> 5;
    const int row  = tid >> 1;        // 0..63 : query row owned (softmax/O phases)
    const int half = tid & 1;         // d-half for O
    const size_t base = (size_t)bh * TT * DH;
    const int q0 = qt * 64;

    // Load + split Q (scaled)
    for (int i = tid; i < 64 * 16; i += 128) {
        int r = i >> 4, c4 = (i & 15) << 2;
        float4 v = *(const float4*)(g_q + base + (size_t)(q0 + r) * DH + c4);
        float vv[4] = {v.x * 0.125f, v.y * 0.125f, v.z * 0.125f, v.w * 0.125f};
#pragma unroll
        for (int u = 0; u < 4; u++) {
            __nv_bfloat16 hb = __float2bfloat16(vv[u]);
            Qh[r * LDB + c4 + u] = hb;
            Ql[r * LDB + c4 + u] = __float2bfloat16(vv[u] - __bfloat162float(hb));
        }
    }
    if (tid < 64) { mrow[tid] = -1e30f; lrow[tid] = 0.f; }

    float o[32];
#pragma unroll
    for (int j = 0; j < 32; j++) o[j] = 0.f;

    const int ntiles = qt + 1;
    for (int kt = 0; kt < ntiles; kt++) {
        __syncthreads();
        // Load K (split hi/lo) and V
        for (int i = tid; i < 64 * 16; i += 128) {
            int r = i >> 4, c4 = (i & 15) << 2;
            size_t g = base + (size_t)(kt * 64 + r) * DH + c4;
            float4 kv = *(const float4*)(g_k + g);
            float kk[4] = {kv.x, kv.y, kv.z, kv.w};
#pragma unroll
            for (int u = 0; u < 4; u++) {
                __nv_bfloat16 hb = __float2bfloat16(kk[u]);
                Kh[r * LDB + c4 + u] = hb;
                Kl[r * LDB + c4 + u] = __float2bfloat16(kk[u] - __bfloat162float(hb));
            }
            *(float4*)(Vs + r * LDF + c4) = *(const float4*)(g_v + g);
        }
        __syncthreads();

        // S = Q*K^T : warp computes rows [warp*16, +16) x 64 cols
        {
            wmma::fragment<wmma::accumulator, 16, 16, 16, float> acc[4];
#pragma unroll
            for (int nc = 0; nc < 4; nc++) wmma::fill_fragment(acc[nc], 0.f);
#pragma unroll
            for (int dc = 0; dc < 4; dc++) {
                wmma::fragment<wmma::matrix_a, 16, 16, 16, __nv_bfloat16, wmma::row_major> ah, al;
                wmma::load_matrix_sync(ah, Qh + (warp * 16) * LDB + dc * 16, LDB);
                wmma::load_matrix_sync(al, Ql + (warp * 16) * LDB + dc * 16, LDB);
#pragma unroll
                for (int nc = 0; nc < 4; nc++) {
                    wmma::fragment<wmma::matrix_b, 16, 16, 16, __nv_bfloat16, wmma::col_major> bh_, bl_;
                    wmma::load_matrix_sync(bh_, Kh + (nc * 16) * LDB + dc * 16, LDB);
                    wmma::load_matrix_sync(bl_, Kl + (nc * 16) * LDB + dc * 16, LDB);
                    wmma::mma_sync(acc[nc], ah, bh_, acc[nc]);
                    wmma::mma_sync(acc[nc], ah, bl_, acc[nc]);
                    wmma::mma_sync(acc[nc], al, bh_, acc[nc]);
                }
            }
#pragma unroll
            for (int nc = 0; nc < 4; nc++)
                wmma::store_matrix_sync(Ps + (warp * 16) * LDF + nc * 16, acc[nc],
                                        LDF, wmma::mem_row_major);
        }
        __syncthreads();

        // Online softmax on Ps; thread-pair per row, each half scans 32 cols
        {
            int jlim = q0 + row - kt * 64 + 1;          // #valid cols in this tile
            jlim = jlim < 0 ? 0 : (jlim > 64 ? 64 : jlim);
            float tmax = -1e30f;
            const float* pr = Ps + row * LDF + half * 32;
#pragma unroll
            for (int c = 0; c < 32; c++) {
                int cg = half * 32 + c;
                float s = pr[c];
                if (cg < jlim) tmax = fmaxf(tmax, s);
            }
            tmax = fmaxf(tmax, __shfl_xor_sync(0xffffffff, tmax, 1));
            float mold = mrow[row];
            float mnew = fmaxf(mold, tmax);
            float f = fexp2((mold - mnew) * LOG2E);
            float lsum = 0.f;
            float* pw = Ps + row * LDF + half * 32;
#pragma unroll
            for (int c = 0; c < 32; c++) {
                int cg = half * 32 + c;
                float p = (cg < jlim) ? fexp2((pw[c] - mnew) * LOG2E) : 0.f;
                pw[c] = p;
                lsum += p;
            }
            lsum += __shfl_xor_sync(0xffffffff, lsum, 1);
            if (half == 0) {
                mrow[row] = mnew;
                lrow[row] = lrow[row] * f + lsum;
            }
#pragma unroll
            for (int j = 0; j < 32; j++) o[j] *= f;
        }
        __syncthreads();

        // PV = P * V (tf32): warp computes rows [warp*16,+16) x 64 d
        {
            wmma::fragment<wmma::accumulator, 16, 16, 8, float> pacc[4];
#pragma unroll
            for (int nc = 0; nc < 4; nc++) wmma::fill_fragment(pacc[nc], 0.f);
#pragma unroll
            for (int kc = 0; kc < 8; kc++) {
                wmma::fragment<wmma::matrix_a, 16, 16, 8, wmma::precision::tf32, wmma::row_major> af;
                wmma::load_matrix_sync(af, Ps + (warp * 16) * LDF + kc * 8, LDF);
#pragma unroll
                for (int e = 0; e < af.num_elements; e++)
                    af.x[e] = wmma::__float_to_tf32(af.x[e]);
#pragma unroll
                for (int nc = 0; nc < 4; nc++) {
                    wmma::fragment<wmma::matrix_b, 16, 16, 8, wmma::precision::tf32, wmma::row_major> bf;
                    wmma::load_matrix_sync(bf, Vs + (kc * 8) * LDF + nc * 16, LDF);
#pragma unroll
                    for (int e = 0; e < bf.num_elements; e++)
                        bf.x[e] = wmma::__float_to_tf32(bf.x[e]);
                    wmma::mma_sync(pacc[nc], af, bf, pacc[nc]);
                }
            }
#pragma unroll
            for (int nc = 0; nc < 4; nc++)
                wmma::store_matrix_sync(PV + (warp * 16) * LDF + nc * 16, pacc[nc],
                                        LDF, wmma::mem_row_major);
        }
        __syncthreads();

        // O += PV (registers)
        {
            const float* pv = PV + row * LDF + half * 32;
#pragma unroll
            for (int j = 0; j < 32; j++) o[j] += pv[j];
        }
    }
    __syncthreads();

    // Epilogue: normalize, write to g_y [B,T,C]
    {
        float inv = 1.0f / lrow[row];
        int b = bh / NH, h = bh % NH;
        int t = q0 + row;
        float* yp = g_y + ((size_t)(b * TT + t)) * DM + h * DH + half * 32;
#pragma unroll
        for (int j4 = 0; j4 < 8; j4++) {
            float4 v = make_float4(o[j4*4+0]*inv, o[j4*4+1]*inv,
                                   o[j4*4+2]*inv, o[j4*4+3]*inv);
            *(float4*)(yp + j4 * 4) = v;
        }
    }
}

// ---------------- launch -----------------------------------------------------------
extern "C" void kernel_launch(void* const* d_in, const int* in_sizes, int n_in,
                              void* d_out, int out_size)
{
    const float *x = nullptr, *wa = nullptr, *ba = nullptr, *wp = nullptr, *bp = nullptr;
    for (int divi = 0; divi < 2; divi++) {
        long long div = (divi == 0) ? 1 : 4;
        const float *tx=nullptr,*twa=nullptr,*tba=nullptr,*twp=nullptr,*tbp=nullptr;
        for (int i = 0; i < n_in; i++) {
            long long s = (long long)in_sizes[i] / div;
            if      (s == 3145728) tx  = (const float*)d_in[i];
            else if (s == 1769472) twa = (const float*)d_in[i];
            else if (s == 589824)  twp = (const float*)d_in[i];
            else if (s == 2304)    tba = (const float*)d_in[i];
            else if (s == 768)     tbp = (const float*)d_in[i];
        }
        if (tx && twa && tba && twp && tbp) { x=tx; wa=twa; ba=tba; wp=twp; bp=tbp; break; }
    }
    if (!(x && wa && ba && wp && bp)) return;

    float* out = (float*)d_out;

    cudaFuncSetAttribute(attn_tc, cudaFuncAttributeMaxDynamicSharedMemorySize, ATT_SMEM);

    // 1) QKV projection (tf32 TC) -> q/k/v [B,H,T,D]
    {
        dim3 grid(NQKV / BN, MROWS / BM);   // (36, 32)
        gemm_tc<1><<<grid, 256>>>(x, wa, ba, nullptr, NQKV, DM);
    }
    // 2) causal attention (TC flash) -> g_y [B,T,C]
    {
        dim3 grid(TT / 64, BB * NH);        // (32, 24)
        attn_tc<<<grid, 128, ATT_SMEM>>>();
    }
    // 3) output projection (tf32 TC, A=g_y bound in device code)
    {
        dim3 grid(DM / BN, MROWS / BM);     // (12, 32)
        gemm_tc<2><<<grid, 256>>>(nullptr, wp, bp, out, DM, DM);
    }
}

// round 11
// speedup vs baseline: 2.8000x; 1.5601x over previous
#include <cuda_runtime.h>
#include <cuda_bf16.h>
#include <mma.h>
#include <cstdint>

using namespace nvcuda;

#define BB 2
#define TT 2048
#define NH 12
#define DH 64
#define DM 768
#define NQKV (3*DM)
#define MROWS (BB*TT)   // 4096

// Scratch (allocation-free). NOTE: never pass these symbols from host code —
// GB300 ATS silently resolves the host shadow address (reads zeros).
__device__ __align__(16) __nv_bfloat16 g_qh[(size_t)BB*NH*TT*DH];
__device__ __align__(16) __nv_bfloat16 g_ql[(size_t)BB*NH*TT*DH];
__device__ __align__(16) __nv_bfloat16 g_kh[(size_t)BB*NH*TT*DH];
__device__ __align__(16) __nv_bfloat16 g_kl[(size_t)BB*NH*TT*DH];
__device__ __align__(16) __nv_bfloat16 g_vth[(size_t)BB*NH*DH*TT];  // [B,H,D,T]
__device__ __align__(16) __nv_bfloat16 g_vtl[(size_t)BB*NH*DH*TT];
__device__ __align__(16) float g_y[(size_t)MROWS*DM];

// ---------------- tf32 tensor-core GEMM --------------------------------------------
#define BM 128
#define BN 64
#define BK 16
#define AKP 20
#define BNP 72
#define CNP 68

__device__ __forceinline__ void split_bf16(float v, __nv_bfloat16& hi, __nv_bfloat16& lo)
{
    hi = __float2bfloat16(v);
    lo = __float2bfloat16(v - __bfloat162float(hi));
}

// MODE 1: QKV; epilogue pre-scales/splits q,k and splits+transposes v.
// MODE 2: A = g_y (bound in device code), plain store + bias.
template <int MODE>
__global__ __launch_bounds__(256) void gemm_tc(
    const float* __restrict__ A_, const float* __restrict__ Bw,
    const float* __restrict__ bias, float* __restrict__ Cout,
    int N, int K)
{
    const float* __restrict__ A = (MODE == 2) ? (const float*)g_y : A_;

    __shared__ union {
        struct { float As[BM][AKP]; float Bs[BK][BNP]; } ld;
        float Cs[BM][CNP];
    } sm;

    const int tid  = threadIdx.x;
    const int warp = tid >> 5;
    const int wm   = warp & 3;
    const int wn   = warp >> 2;
    const int bm   = blockIdx.y * BM;
    const int bn   = blockIdx.x * BN;

    wmma::fragment<wmma::accumulator, 16, 16, 8, float> acc[2][2];
#pragma unroll
    for (int i = 0; i < 2; i++)
#pragma unroll
        for (int j = 0; j < 2; j++) wmma::fill_fragment(acc[i][j], 0.f);

    for (int k0 = 0; k0 < K; k0 += BK) {
#pragma unroll
        for (int i = 0; i < 2; i++) {
            int idx = tid + i * 256;
            int r = idx >> 2;
            int c4 = (idx & 3) << 2;
            float4 v = *(const float4*)(A + (size_t)(bm + r) * K + k0 + c4);
            *(float4*)&sm.ld.As[r][c4] = v;
        }
        {
            int r = tid >> 4;
            int c4 = (tid & 15) << 2;
            float4 v = *(const float4*)(Bw + (size_t)(k0 + r) * N + bn + c4);
            *(float4*)&sm.ld.Bs[r][c4] = v;
        }
        __syncthreads();

#pragma unroll
        for (int ks = 0; ks < BK; ks += 8) {
            wmma::fragment<wmma::matrix_a, 16, 16, 8, wmma::precision::tf32, wmma::row_major> af[2];
            wmma::fragment<wmma::matrix_b, 16, 16, 8, wmma::precision::tf32, wmma::row_major> bf[2];
#pragma unroll
            for (int i = 0; i < 2; i++) {
                wmma::load_matrix_sync(af[i], &sm.ld.As[wm * 32 + i * 16][ks], AKP);
#pragma unroll
                for (int e = 0; e < af[i].num_elements; e++)
                    af[i].x[e] = wmma::__float_to_tf32(af[i].x[e]);
            }
#pragma unroll
            for (int j = 0; j < 2; j++) {
                wmma::load_matrix_sync(bf[j], &sm.ld.Bs[ks][wn * 32 + j * 16], BNP);
#pragma unroll
                for (int e = 0; e < bf[j].num_elements; e++)
                    bf[j].x[e] = wmma::__float_to_tf32(bf[j].x[e]);
            }
#pragma unroll
            for (int i = 0; i < 2; i++)
#pragma unroll
                for (int j = 0; j < 2; j++)
                    wmma::mma_sync(acc[i][j], af[i], bf[j], acc[i][j]);
        }
        __syncthreads();
    }

#pragma unroll
    for (int i = 0; i < 2; i++)
#pragma unroll
        for (int j = 0; j < 2; j++)
            wmma::store_matrix_sync(&sm.Cs[wm * 32 + i * 16][wn * 32 + j * 16],
                                    acc[i][j], CNP, wmma::mem_row_major);
    __syncthreads();

    if (MODE != 1) {
#pragma unroll
        for (int it = 0; it < 32; it++) {
            int idx = tid + it * 256;
            int r = idx >> 6;
            int n_loc = idx & 63;
            Cout[(size_t)(bm + r) * N + bn + n_loc] = sm.Cs[r][n_loc] + bias[bn + n_loc];
        }
    } else {
        // Whole block = one (which, head): BN=64 aligns with DH.
        const int which = bn / DM;
        const int hd    = bn % DM;
        const int h     = hd / DH;
        const int b     = bm / TT;      // BM=128 divides TT
        const int t0    = bm % TT;
        const int bh    = b * NH + h;

        if (which == 2) {
            // V: transposed split store  g_vt*[bh][d][t]
#pragma unroll
            for (int it = 0; it < 4; it++) {
                int cid = tid + it * 256;       // 1024 chunks
                int d   = cid >> 4;             // 0..63
                int tc  = (cid & 15) * 8;       // token chunk
                float bval = bias[bn + d];
                __nv_bfloat16 hb[8], lb[8];
#pragma unroll
                for (int j = 0; j < 8; j++)
                    split_bf16(sm.Cs[tc + j][d] + bval, hb[j], lb[j]);
                size_t dst = ((size_t)bh * DH + d) * TT + t0 + tc;
                *(uint4*)(g_vth + dst) = *(uint4*)hb;
                *(uint4*)(g_vtl + dst) = *(uint4*)lb;
            }
        } else {
            const float qscale = (which == 0) ? 0.125f : 1.0f;
            __nv_bfloat16* dh = (which == 0) ? g_qh : g_kh;
            __nv_bfloat16* dl = (which == 0) ? g_ql : g_kl;
#pragma unroll
            for (int it = 0; it < 4; it++) {
                int cid = tid + it * 256;       // 1024 chunks
                int r   = cid >> 3;             // 0..127 token row
                int c8  = (cid & 7) * 8;        // d chunk
                __nv_bfloat16 hb[8], lb[8];
#pragma unroll
                for (int j = 0; j < 8; j++) {
                    float v = (sm.Cs[r][c8 + j] + bias[bn + c8 + j]) * qscale;
                    split_bf16(v, hb[j], lb[j]);
                }
                size_t dst = ((size_t)bh * TT + t0 + r) * DH + c8;
                *(uint4*)(dh + dst) = *(uint4*)hb;
                *(uint4*)(dl + dst) = *(uint4*)lb;
            }
        }
    }
}

// ---------------- Register-resident flash attention (raw mma.m16n8k16) -------------
#define LOG2E 1.4426950408889634f
#define LDSB 72      // smem leading dim (bf16 elems)

__device__ __forceinline__ float fexp2(float t)   // t <= 0; returns 2^t
{
    t = fmaxf(t, -126.f);
    float fl = floorf(t);
    float x = (t - fl) * 0.69314718056f;
    float p = 1.f + x*(1.f + x*(0.5f + x*(0.16666667f + x*(0.041666667f
              + x*(0.0083333333f + x*0.0013888889f)))));
    return __int_as_float(__float_as_int(p) + ((int)fl << 23));
}

__device__ __forceinline__ void mma16816(float* c, uint32_t a0, uint32_t a1,
                                         uint32_t a2, uint32_t a3,
                                         uint32_t b0, uint32_t b1)
{
    asm volatile(
        "mma.sync.aligned.m16n8k16.row.col.f32.bf16.bf16.f32 "
        "{%0,%1,%2,%3}, {%4,%5,%6,%7}, {%8,%9}, {%0,%1,%2,%3};\n"
        : "+f"(c[0]), "+f"(c[1]), "+f"(c[2]), "+f"(c[3])
        : "r"(a0), "r"(a1), "r"(a2), "r"(a3), "r"(b0), "r"(b1));
}

__device__ __forceinline__ uint32_t lds32(const __nv_bfloat16* p)
{
    return *(const uint32_t*)p;
}

__device__ __forceinline__ uint32_t packbf(float x, float y)
{
    __nv_bfloat162 h = __floats2bfloat162_rn(x, y);   // .x = low = x
    return *(uint32_t*)&h;
}

// Split two floats into packed bf16 hi and lo words.
__device__ __forceinline__ void packsplit(float x, float y, uint32_t& hi, uint32_t& lo)
{
    __nv_bfloat162 h = __floats2bfloat162_rn(x, y);
    float2 hf = __bfloat1622float2(h);
    __nv_bfloat162 l = __floats2bfloat162_rn(x - hf.x, y - hf.y);
    hi = *(uint32_t*)&h;
    lo = *(uint32_t*)&l;
}

// smem: QH,QL,KH,KL,VTH,VTL : each 64 x LDSB bf16 = 9216 B -> total 55296 B
#define ATT_SMEM (6*64*LDSB*2)

__global__ __launch_bounds__(128) void attn_reg()
{
    extern __shared__ __nv_bfloat16 smb[];
    __nv_bfloat16* QH  = smb;
    __nv_bfloat16* QL  = QH  + 64*LDSB;
    __nv_bfloat16* KH  = QL  + 64*LDSB;
    __nv_bfloat16* KL  = KH  + 64*LDSB;
    __nv_bfloat16* VTH = KL  + 64*LDSB;
    __nv_bfloat16* VTL = VTH + 64*LDSB;

    const int bh   = blockIdx.y;
    const int qt   = gridDim.x - 1 - blockIdx.x;  // heavy first
    const int tid  = threadIdx.x;
    const int warp = tid >> 5;
    const int lane = tid & 31;
    const int g    = lane >> 2;      // group 0..7
    const int t    = lane & 3;       // thread-in-group
    const int q0   = qt * 64;

    const __nv_bfloat16* gqh = g_qh + (size_t)bh * TT * DH;
    const __nv_bfloat16* gql = g_ql + (size_t)bh * TT * DH;
    const __nv_bfloat16* gkh = g_kh + (size_t)bh * TT * DH;
    const __nv_bfloat16* gkl = g_kl + (size_t)bh * TT * DH;
    const __nv_bfloat16* gvh = g_vth + (size_t)bh * DH * TT;
    const __nv_bfloat16* gvl = g_vtl + (size_t)bh * DH * TT;

    // Load Q tile (64 x 64) hi/lo
#pragma unroll
    for (int it = 0; it < 4; it++) {
        int cid = tid + it * 128;       // 512 chunks of 8 bf16
        int r   = cid >> 3;
        int c8  = (cid & 7) * 8;
        *(uint4*)(QH + r * LDSB + c8) = *(const uint4*)(gqh + (size_t)(q0 + r) * DH + c8);
        *(uint4*)(QL + r * LDSB + c8) = *(const uint4*)(gql + (size_t)(q0 + r) * DH + c8);
    }

    float o[8][4];
#pragma unroll
    for (int nt = 0; nt < 8; nt++)
#pragma unroll
        for (int e = 0; e < 4; e++) o[nt][e] = 0.f;
    float m0 = -1e30f, m1 = -1e30f, l0 = 0.f, l1 = 0.f;

    const int rowg  = q0 + warp * 16 + g;
    const int rowg8 = rowg + 8;

    for (int kt = 0; kt <= qt; kt++) {
        __syncthreads();
#pragma unroll
        for (int it = 0; it < 4; it++) {
            int cid = tid + it * 128;
            int r   = cid >> 3;
            int c8  = (cid & 7) * 8;
            *(uint4*)(KH  + r * LDSB + c8) = *(const uint4*)(gkh + (size_t)(kt*64 + r) * DH + c8);
            *(uint4*)(KL  + r * LDSB + c8) = *(const uint4*)(gkl + (size_t)(kt*64 + r) * DH + c8);
            *(uint4*)(VTH + r * LDSB + c8) = *(const uint4*)(gvh + (size_t)r * TT + kt*64 + c8);
            *(uint4*)(VTL + r * LDSB + c8) = *(const uint4*)(gvl + (size_t)r * TT + kt*64 + c8);
        }
        __syncthreads();

        // ---- S = Q K^T (3-term bf16), accumulators in registers ----
        float s[8][4];
#pragma unroll
        for (int nt = 0; nt < 8; nt++)
#pragma unroll
            for (int e = 0; e < 4; e++) s[nt][e] = 0.f;

#pragma unroll
        for (int kc = 0; kc < 4; kc++) {
            const int qrow = warp * 16 + g;
            const int dlo  = kc * 16 + 2 * t;
            uint32_t ah0 = lds32(QH + qrow * LDSB + dlo);
            uint32_t ah1 = lds32(QH + (qrow + 8) * LDSB + dlo);
            uint32_t ah2 = lds32(QH + qrow * LDSB + dlo + 8);
            uint32_t ah3 = lds32(QH + (qrow + 8) * LDSB + dlo + 8);
            uint32_t al0 = lds32(QL + qrow * LDSB + dlo);
            uint32_t al1 = lds32(QL + (qrow + 8) * LDSB + dlo);
            uint32_t al2 = lds32(QL + qrow * LDSB + dlo + 8);
            uint32_t al3 = lds32(QL + (qrow + 8) * LDSB + dlo + 8);
#pragma unroll
            for (int nt = 0; nt < 8; nt++) {
                const int krow = nt * 8 + g;
                uint32_t bh0 = lds32(KH + krow * LDSB + dlo);
                uint32_t bh1 = lds32(KH + krow * LDSB + dlo + 8);
                uint32_t bl0 = lds32(KL + krow * LDSB + dlo);
                uint32_t bl1 = lds32(KL + krow * LDSB + dlo + 8);
                mma16816(s[nt], ah0, ah1, ah2, ah3, bh0, bh1);
                mma16816(s[nt], al0, al1, al2, al3, bh0, bh1);
                mma16816(s[nt], ah0, ah1, ah2, ah3, bl0, bl1);
            }
        }

        // ---- causal mask on the diagonal tile ----
        if (kt == qt) {
#pragma unroll
            for (int nt = 0; nt < 8; nt++) {
                int c0 = kt * 64 + nt * 8 + 2 * t;
                if (c0     > rowg)  s[nt][0] = -1e30f;
                if (c0 + 1 > rowg)  s[nt][1] = -1e30f;
                if (c0     > rowg8) s[nt][2] = -1e30f;
                if (c0 + 1 > rowg8) s[nt][3] = -1e30f;
            }
        }

        // ---- online softmax in registers ----
        float tmax0 = -1e30f, tmax1 = -1e30f;
#pragma unroll
        for (int nt = 0; nt < 8; nt++) {
            tmax0 = fmaxf(tmax0, fmaxf(s[nt][0], s[nt][1]));
            tmax1 = fmaxf(tmax1, fmaxf(s[nt][2], s[nt][3]));
        }
        tmax0 = fmaxf(tmax0, __shfl_xor_sync(0xffffffff, tmax0, 1));
        tmax0 = fmaxf(tmax0, __shfl_xor_sync(0xffffffff, tmax0, 2));
        tmax1 = fmaxf(tmax1, __shfl_xor_sync(0xffffffff, tmax1, 1));
        tmax1 = fmaxf(tmax1, __shfl_xor_sync(0xffffffff, tmax1, 2));

        float mnew0 = fmaxf(m0, tmax0);
        float mnew1 = fmaxf(m1, tmax1);
        float f0 = fexp2((m0 - mnew0) * LOG2E);
        float f1 = fexp2((m1 - mnew1) * LOG2E);

        // P split hi/lo so PV is ~fp32-accurate
        uint32_t pah[4][4], pal[4][4];
        float ls0 = 0.f, ls1 = 0.f;
#pragma unroll
        for (int kc = 0; kc < 4; kc++) {
            float p00 = fexp2((s[2*kc][0]   - mnew0) * LOG2E);
            float p01 = fexp2((s[2*kc][1]   - mnew0) * LOG2E);
            float p02 = fexp2((s[2*kc][2]   - mnew1) * LOG2E);
            float p03 = fexp2((s[2*kc][3]   - mnew1) * LOG2E);
            float p10 = fexp2((s[2*kc+1][0] - mnew0) * LOG2E);
            float p11 = fexp2((s[2*kc+1][1] - mnew0) * LOG2E);
            float p12 = fexp2((s[2*kc+1][2] - mnew1) * LOG2E);
            float p13 = fexp2((s[2*kc+1][3] - mnew1) * LOG2E);
            packsplit(p00, p01, pah[kc][0], pal[kc][0]);   // row g,   keys lo
            packsplit(p02, p03, pah[kc][1], pal[kc][1]);   // row g+8, keys lo
            packsplit(p10, p11, pah[kc][2], pal[kc][2]);   // row g,   keys hi
            packsplit(p12, p13, pah[kc][3], pal[kc][3]);   // row g+8, keys hi
            ls0 += (p00 + p01) + (p10 + p11);
            ls1 += (p02 + p03) + (p12 + p13);
        }
        ls0 += __shfl_xor_sync(0xffffffff, ls0, 1);
        ls0 += __shfl_xor_sync(0xffffffff, ls0, 2);
        ls1 += __shfl_xor_sync(0xffffffff, ls1, 1);
        ls1 += __shfl_xor_sync(0xffffffff, ls1, 2);

        l0 = l0 * f0 + ls0;  m0 = mnew0;
        l1 = l1 * f1 + ls1;  m1 = mnew1;

#pragma unroll
        for (int nt = 0; nt < 8; nt++) {
            o[nt][0] *= f0; o[nt][1] *= f0;
            o[nt][2] *= f1; o[nt][3] *= f1;
        }

        // ---- O += P * V : Ph*Vh + Pl*Vh + Ph*Vl (fp32-accurate) ----
#pragma unroll
        for (int kc = 0; kc < 4; kc++) {
            const int klo = kc * 16 + 2 * t;
#pragma unroll
            for (int nt = 0; nt < 8; nt++) {
                const int drow = nt * 8 + g;
                uint32_t vh0 = lds32(VTH + drow * LDSB + klo);
                uint32_t vh1 = lds32(VTH + drow * LDSB + klo + 8);
                uint32_t vl0 = lds32(VTL + drow * LDSB + klo);
                uint32_t vl1 = lds32(VTL + drow * LDSB + klo + 8);
                mma16816(o[nt], pah[kc][0], pah[kc][1], pah[kc][2], pah[kc][3], vh0, vh1);
                mma16816(o[nt], pal[kc][0], pal[kc][1], pal[kc][2], pal[kc][3], vh0, vh1);
                mma16816(o[nt], pah[kc][0], pah[kc][1], pah[kc][2], pah[kc][3], vl0, vl1);
            }
        }
    }

    // ---- epilogue: normalize + write g_y [B,T,C] ----
    {
        float inv0 = 1.0f / l0;
        float inv1 = 1.0f / l1;
        int b = bh / NH, h = bh % NH;
        float* y0 = g_y + ((size_t)(b * TT + rowg))  * DM + h * DH;
        float* y1 = g_y + ((size_t)(b * TT + rowg8)) * DM + h * DH;
#pragma unroll
        for (int nt = 0; nt < 8; nt++) {
            int d = nt * 8 + 2 * t;
            *(float2*)(y0 + d) = make_float2(o[nt][0] * inv0, o[nt][1] * inv0);
            *(float2*)(y1 + d) = make_float2(o[nt][2] * inv1, o[nt][3] * inv1);
        }
    }
}

// ---------------- launch -----------------------------------------------------------
extern "C" void kernel_launch(void* const* d_in, const int* in_sizes, int n_in,
                              void* d_out, int out_size)
{
    const float *x = nullptr, *wa = nullptr, *ba = nullptr, *wp = nullptr, *bp = nullptr;
    for (int divi = 0; divi < 2; divi++) {
        long long div = (divi == 0) ? 1 : 4;
        const float *tx=nullptr,*twa=nullptr,*tba=nullptr,*twp=nullptr,*tbp=nullptr;
        for (int i = 0; i < n_in; i++) {
            long long s = (long long)in_sizes[i] / div;
            if      (s == 3145728) tx  = (const float*)d_in[i];
            else if (s == 1769472) twa = (const float*)d_in[i];
            else if (s == 589824)  twp = (const float*)d_in[i];
            else if (s == 2304)    tba = (const float*)d_in[i];
            else if (s == 768)     tbp = (const float*)d_in[i];
        }
        if (tx && twa && tba && twp && tbp) { x=tx; wa=twa; ba=tba; wp=twp; bp=tbp; break; }
    }
    if (!(x && wa && ba && wp && bp)) return;

    float* out = (float*)d_out;

    cudaFuncSetAttribute(attn_reg, cudaFuncAttributeMaxDynamicSharedMemorySize, ATT_SMEM);

    // 1) QKV projection (tf32 TC) -> split/transposed q,k,v bf16 buffers
    {
        dim3 grid(NQKV / BN, MROWS / BM);   // (36, 32)
        gemm_tc<1><<<grid, 256>>>(x, wa, ba, nullptr, NQKV, DM);
    }
    // 2) causal attention (register-resident mma) -> g_y [B,T,C]
    {
        dim3 grid(TT / 64, BB * NH);        // (32, 24)
        attn_reg<<<grid, 128, ATT_SMEM>>>();
    }
    // 3) output projection (tf32 TC, A=g_y bound in device code)
    {
        dim3 grid(DM / BN, MROWS / BM);     // (12, 32)
        gemm_tc<2><<<grid, 256>>>(nullptr, wp, bp, out, DM, DM);
    }
}

// round 12
// speedup vs baseline: 3.1947x; 1.1410x over previous
#include <cuda_runtime.h>
#include <cuda_bf16.h>
#include <cstdint>

#define BB 2
#define TT 2048
#define NH 12
#define DH 64
#define DM 768
#define NQKV (3*DM)
#define MROWS (BB*TT)   // 4096

// Scratch (allocation-free). NOTE: never pass these symbols from host code —
// GB300 ATS silently resolves the host shadow address (reads zeros).
// All GEMM operands pre-split to bf16 hi/lo; weights pre-transposed to [N,K].
__device__ __align__(16) __nv_bfloat16 g_xh [(size_t)MROWS*DM];
__device__ __align__(16) __nv_bfloat16 g_xl [(size_t)MROWS*DM];
__device__ __align__(16) __nv_bfloat16 g_wath[(size_t)NQKV*DM];   // [2304,768]
__device__ __align__(16) __nv_bfloat16 g_watl[(size_t)NQKV*DM];
__device__ __align__(16) __nv_bfloat16 g_wpth[(size_t)DM*DM];     // [768,768]
__device__ __align__(16) __nv_bfloat16 g_wptl[(size_t)DM*DM];
__device__ __align__(16) __nv_bfloat16 g_qh[(size_t)BB*NH*TT*DH];
__device__ __align__(16) __nv_bfloat16 g_ql[(size_t)BB*NH*TT*DH];
__device__ __align__(16) __nv_bfloat16 g_kh[(size_t)BB*NH*TT*DH];
__device__ __align__(16) __nv_bfloat16 g_kl[(size_t)BB*NH*TT*DH];
__device__ __align__(16) __nv_bfloat16 g_vth[(size_t)BB*NH*DH*TT];  // [B,H,D,T]
__device__ __align__(16) __nv_bfloat16 g_vtl[(size_t)BB*NH*DH*TT];
__device__ __align__(16) __nv_bfloat16 g_yh[(size_t)MROWS*DM];
__device__ __align__(16) __nv_bfloat16 g_yl[(size_t)MROWS*DM];

// ---------------- helpers ----------------------------------------------------------
__device__ __forceinline__ void split_bf16(float v, __nv_bfloat16& hi, __nv_bfloat16& lo)
{
    hi = __float2bfloat16(v);
    lo = __float2bfloat16(v - __bfloat162float(hi));
}

__device__ __forceinline__ void mma16816(float* c, uint32_t a0, uint32_t a1,
                                         uint32_t a2, uint32_t a3,
                                         uint32_t b0, uint32_t b1)
{
    asm volatile(
        "mma.sync.aligned.m16n8k16.row.col.f32.bf16.bf16.f32 "
        "{%0,%1,%2,%3}, {%4,%5,%6,%7}, {%8,%9}, {%0,%1,%2,%3};\n"
        : "+f"(c[0]), "+f"(c[1]), "+f"(c[2]), "+f"(c[3])
        : "r"(a0), "r"(a1), "r"(a2), "r"(a3), "r"(b0), "r"(b1));
}

__device__ __forceinline__ uint32_t lds32(const __nv_bfloat16* p)
{
    return *(const uint32_t*)p;
}

__device__ __forceinline__ void packsplit(float x, float y, uint32_t& hi, uint32_t& lo)
{
    __nv_bfloat162 h = __floats2bfloat162_rn(x, y);
    float2 hf = __bfloat1622float2(h);
    __nv_bfloat162 l = __floats2bfloat162_rn(x - hf.x, y - hf.y);
    hi = *(uint32_t*)&h;
    lo = *(uint32_t*)&l;
}

// ---------------- input split kernels ----------------------------------------------
__global__ __launch_bounds__(256) void split_x(const float* __restrict__ x)
{
    size_t i = ((size_t)blockIdx.x * 256 + threadIdx.x) * 8;
    float4 v0 = *(const float4*)(x + i);
    float4 v1 = *(const float4*)(x + i + 4);
    float vv[8] = {v0.x, v0.y, v0.z, v0.w, v1.x, v1.y, v1.z, v1.w};
    __nv_bfloat16 h[8], l[8];
#pragma unroll
    for (int j = 0; j < 8; j++) split_bf16(vv[j], h[j], l[j]);
    *(uint4*)(g_xh + i) = *(uint4*)h;
    *(uint4*)(g_xl + i) = *(uint4*)l;
}

// Transpose+split weight [768, N] -> [N, 768] hi/lo.  W=0: w_attn, W=1: w_proj
template <int W>
__global__ __launch_bounds__(256) void splitT_w(const float* __restrict__ w, int N)
{
    __shared__ float ts[32][33];
    const int tx = threadIdx.x & 31, ty = threadIdx.x >> 5;  // 32 x 8
    const int n0 = blockIdx.x * 32, k0 = blockIdx.y * 32;
#pragma unroll
    for (int i = 0; i < 4; i++) {
        int ky = ty + i * 8;
        ts[ky][tx] = w[(size_t)(k0 + ky) * N + n0 + tx];
    }
    __syncthreads();
    __nv_bfloat16* th = (W == 0) ? g_wath : g_wpth;
    __nv_bfloat16* tl = (W == 0) ? g_watl : g_wptl;
#pragma unroll
    for (int i = 0; i < 4; i++) {
        int r = ty + i * 8;                 // local n
        float v = ts[tx][r];
        __nv_bfloat16 hi, lo;
        split_bf16(v, hi, lo);
        th[(size_t)(n0 + r) * DM + k0 + tx] = hi;
        tl[(size_t)(n0 + r) * DM + k0 + tx] = lo;
    }
}

// ---------------- 3-term bf16 raw-mma GEMM ------------------------------------------
// C[M,N] = A*B^T + bias (B stored transposed [N,K]).  Tiles: 128x64xK32, 256 thr.
// MODE 1: A = x (g_xh/g_xl), B = w_attn; epilogue scatter-splits q/k/v.
// MODE 2: A = y (g_yh/g_yl), B = w_proj; plain fp32 store + bias.
#define GM 128
#define GN 64
#define GKT 32
#define GLD 40
#define GCN 68

template <int MODE>
__global__ __launch_bounds__(256) void gemm_bf(const float* __restrict__ bias,
                                               float* __restrict__ Cout, int N)
{
    constexpr int K = DM;
    const __nv_bfloat16* __restrict__ Ah = (MODE == 1) ? g_xh : g_yh;
    const __nv_bfloat16* __restrict__ Al = (MODE == 1) ? g_xl : g_yl;
    const __nv_bfloat16* __restrict__ Bh = (MODE == 1) ? g_wath : g_wpth;
    const __nv_bfloat16* __restrict__ Bl = (MODE == 1) ? g_watl : g_wptl;

    __shared__ union {
        struct {
            __nv_bfloat16 AH[GM][GLD], AL[GM][GLD];
            __nv_bfloat16 BH[GN][GLD], BL[GN][GLD];
        } ld;
        float Cs[GM][GCN];
    } sm;

    const int tid  = threadIdx.x;
    const int warp = tid >> 5, lane = tid & 31;
    const int g = lane >> 2, t = lane & 3;
    const int m0 = (warp & 3) * 32, n0 = (warp >> 2) * 32;
    const int bm = blockIdx.y * GM, bn = blockIdx.x * GN;

    float acc[2][4][4] = {};

    for (int k0 = 0; k0 < K; k0 += GKT) {
        __syncthreads();
#pragma unroll
        for (int i = 0; i < 2; i++) {
            int cid = tid + i * 256;
            int r = cid >> 2, c8 = (cid & 3) * 8;
            size_t src = (size_t)(bm + r) * K + k0 + c8;
            *(uint4*)&sm.ld.AH[r][c8] = *(const uint4*)(Ah + src);
            *(uint4*)&sm.ld.AL[r][c8] = *(const uint4*)(Al + src);
        }
        {
            int r = tid >> 2, c8 = (tid & 3) * 8;
            size_t src = (size_t)(bn + r) * K + k0 + c8;
            *(uint4*)&sm.ld.BH[r][c8] = *(const uint4*)(Bh + src);
            *(uint4*)&sm.ld.BL[r][c8] = *(const uint4*)(Bl + src);
        }
        __syncthreads();

#pragma unroll
        for (int kc = 0; kc < 2; kc++) {
            const int dlo = kc * 16 + 2 * t;
            uint32_t aH[2][4], aL[2][4];
#pragma unroll
            for (int mi = 0; mi < 2; mi++) {
                int r0 = m0 + mi * 16 + g, r1 = r0 + 8;
                aH[mi][0] = lds32(&sm.ld.AH[r0][dlo]);
                aH[mi][1] = lds32(&sm.ld.AH[r1][dlo]);
                aH[mi][2] = lds32(&sm.ld.AH[r0][dlo + 8]);
                aH[mi][3] = lds32(&sm.ld.AH[r1][dlo + 8]);
                aL[mi][0] = lds32(&sm.ld.AL[r0][dlo]);
                aL[mi][1] = lds32(&sm.ld.AL[r1][dlo]);
                aL[mi][2] = lds32(&sm.ld.AL[r0][dlo + 8]);
                aL[mi][3] = lds32(&sm.ld.AL[r1][dlo + 8]);
            }
#pragma unroll
            for (int ni = 0; ni < 4; ni++) {
                int rn = n0 + ni * 8 + g;
                uint32_t bh0 = lds32(&sm.ld.BH[rn][dlo]);
                uint32_t bh1 = lds32(&sm.ld.BH[rn][dlo + 8]);
                uint32_t bl0 = lds32(&sm.ld.BL[rn][dlo]);
                uint32_t bl1 = lds32(&sm.ld.BL[rn][dlo + 8]);
#pragma unroll
                for (int mi = 0; mi < 2; mi++) {
                    mma16816(acc[mi][ni], aH[mi][0], aH[mi][1], aH[mi][2], aH[mi][3], bh0, bh1);
                    mma16816(acc[mi][ni], aL[mi][0], aL[mi][1], aL[mi][2], aL[mi][3], bh0, bh1);
                    mma16816(acc[mi][ni], aH[mi][0], aH[mi][1], aH[mi][2], aH[mi][3], bl0, bl1);
                }
            }
        }
    }

    __syncthreads();
#pragma unroll
    for (int mi = 0; mi < 2; mi++)
#pragma unroll
        for (int ni = 0; ni < 4; ni++) {
            int r = m0 + mi * 16 + g, c = n0 + ni * 8 + 2 * t;
            *(float2*)&sm.Cs[r][c]     = make_float2(acc[mi][ni][0], acc[mi][ni][1]);
            *(float2*)&sm.Cs[r + 8][c] = make_float2(acc[mi][ni][2], acc[mi][ni][3]);
        }
    __syncthreads();

    if (MODE == 2) {
#pragma unroll
        for (int it = 0; it < 32; it++) {
            int idx = tid + it * 256;
            int r = idx >> 6;
            int n_loc = idx & 63;
            Cout[(size_t)(bm + r) * N + bn + n_loc] = sm.Cs[r][n_loc] + bias[bn + n_loc];
        }
    } else {
        // Whole block = one (which, head): GN=64 aligns with DH.
        const int which = bn / DM;
        const int hd    = bn % DM;
        const int h     = hd / DH;
        const int b     = bm / TT;
        const int t0    = bm % TT;
        const int bh    = b * NH + h;

        if (which == 2) {
            // V: transposed split store  g_vt*[bh][d][t]
#pragma unroll
            for (int it = 0; it < 4; it++) {
                int cid = tid + it * 256;
                int d   = cid >> 4;
                int tc  = (cid & 15) * 8;
                float bval = bias[bn + d];
                __nv_bfloat16 hb[8], lb[8];
#pragma unroll
                for (int j = 0; j < 8; j++)
                    split_bf16(sm.Cs[tc + j][d] + bval, hb[j], lb[j]);
                size_t dst = ((size_t)bh * DH + d) * TT + t0 + tc;
                *(uint4*)(g_vth + dst) = *(uint4*)hb;
                *(uint4*)(g_vtl + dst) = *(uint4*)lb;
            }
        } else {
            const float qscale = (which == 0) ? 0.125f : 1.0f;
            __nv_bfloat16* dh = (which == 0) ? g_qh : g_kh;
            __nv_bfloat16* dl = (which == 0) ? g_ql : g_kl;
#pragma unroll
            for (int it = 0; it < 4; it++) {
                int cid = tid + it * 256;
                int r   = cid >> 3;
                int c8  = (cid & 7) * 8;
                __nv_bfloat16 hb[8], lb[8];
#pragma unroll
                for (int j = 0; j < 8; j++) {
                    float v = (sm.Cs[r][c8 + j] + bias[bn + c8 + j]) * qscale;
                    split_bf16(v, hb[j], lb[j]);
                }
                size_t dst = ((size_t)bh * TT + t0 + r) * DH + c8;
                *(uint4*)(dh + dst) = *(uint4*)hb;
                *(uint4*)(dl + dst) = *(uint4*)lb;
            }
        }
    }
}

// ---------------- Register-resident flash attention (raw mma.m16n8k16) -------------
#define LOG2E 1.4426950408889634f
#define LDSB 72

__device__ __forceinline__ float fexp2(float t)   // t <= 0; returns 2^t
{
    t = fmaxf(t, -126.f);
    float fl = floorf(t);
    float x = (t - fl) * 0.69314718056f;
    float p = 1.f + x*(1.f + x*(0.5f + x*(0.16666667f + x*(0.041666667f
              + x*(0.0083333333f + x*0.0013888889f)))));
    return __int_as_float(__float_as_int(p) + ((int)fl << 23));
}

// smem: QH,QL,KH,KL,VTH,VTL : each 64 x LDSB bf16 = 9216 B -> total 55296 B
#define ATT_SMEM (6*64*LDSB*2)

__global__ __launch_bounds__(128) void attn_reg()
{
    extern __shared__ __nv_bfloat16 smb[];
    __nv_bfloat16* QH  = smb;
    __nv_bfloat16* QL  = QH  + 64*LDSB;
    __nv_bfloat16* KH  = QL  + 64*LDSB;
    __nv_bfloat16* KL  = KH  + 64*LDSB;
    __nv_bfloat16* VTH = KL  + 64*LDSB;
    __nv_bfloat16* VTL = VTH + 64*LDSB;

    const int bh   = blockIdx.y;
    const int qt   = gridDim.x - 1 - blockIdx.x;  // heavy first
    const int tid  = threadIdx.x;
    const int warp = tid >> 5;
    const int lane = tid & 31;
    const int g    = lane >> 2;
    const int t    = lane & 3;
    const int q0   = qt * 64;

    const __nv_bfloat16* gqh = g_qh + (size_t)bh * TT * DH;
    const __nv_bfloat16* gql = g_ql + (size_t)bh * TT * DH;
    const __nv_bfloat16* gkh = g_kh + (size_t)bh * TT * DH;
    const __nv_bfloat16* gkl = g_kl + (size_t)bh * TT * DH;
    const __nv_bfloat16* gvh = g_vth + (size_t)bh * DH * TT;
    const __nv_bfloat16* gvl = g_vtl + (size_t)bh * DH * TT;

#pragma unroll
    for (int it = 0; it < 4; it++) {
        int cid = tid + it * 128;
        int r   = cid >> 3;
        int c8  = (cid & 7) * 8;
        *(uint4*)(QH + r * LDSB + c8) = *(const uint4*)(gqh + (size_t)(q0 + r) * DH + c8);
        *(uint4*)(QL + r * LDSB + c8) = *(const uint4*)(gql + (size_t)(q0 + r) * DH + c8);
    }

    float o[8][4];
#pragma unroll
    for (int nt = 0; nt < 8; nt++)
#pragma unroll
        for (int e = 0; e < 4; e++) o[nt][e] = 0.f;
    float m0 = -1e30f, m1 = -1e30f, l0 = 0.f, l1 = 0.f;

    const int rowg  = q0 + warp * 16 + g;
    const int rowg8 = rowg + 8;

    for (int kt = 0; kt <= qt; kt++) {
        __syncthreads();
#pragma unroll
        for (int it = 0; it < 4; it++) {
            int cid = tid + it * 128;
            int r   = cid >> 3;
            int c8  = (cid & 7) * 8;
            *(uint4*)(KH  + r * LDSB + c8) = *(const uint4*)(gkh + (size_t)(kt*64 + r) * DH + c8);
            *(uint4*)(KL  + r * LDSB + c8) = *(const uint4*)(gkl + (size_t)(kt*64 + r) * DH + c8);
            *(uint4*)(VTH + r * LDSB + c8) = *(const uint4*)(gvh + (size_t)r * TT + kt*64 + c8);
            *(uint4*)(VTL + r * LDSB + c8) = *(const uint4*)(gvl + (size_t)r * TT + kt*64 + c8);
        }
        __syncthreads();

        float s[8][4];
#pragma unroll
        for (int nt = 0; nt < 8; nt++)
#pragma unroll
            for (int e = 0; e < 4; e++) s[nt][e] = 0.f;

#pragma unroll
        for (int kc = 0; kc < 4; kc++) {
            const int qrow = warp * 16 + g;
            const int dlo  = kc * 16 + 2 * t;
            uint32_t ah0 = lds32(QH + qrow * LDSB + dlo);
            uint32_t ah1 = lds32(QH + (qrow + 8) * LDSB + dlo);
            uint32_t ah2 = lds32(QH + qrow * LDSB + dlo + 8);
            uint32_t ah3 = lds32(QH + (qrow + 8) * LDSB + dlo + 8);
            uint32_t al0 = lds32(QL + qrow * LDSB + dlo);
            uint32_t al1 = lds32(QL + (qrow + 8) * LDSB + dlo);
            uint32_t al2 = lds32(QL + qrow * LDSB + dlo + 8);
            uint32_t al3 = lds32(QL + (qrow + 8) * LDSB + dlo + 8);
#pragma unroll
            for (int nt = 0; nt < 8; nt++) {
                const int krow = nt * 8 + g;
                uint32_t bh0 = lds32(KH + krow * LDSB + dlo);
                uint32_t bh1 = lds32(KH + krow * LDSB + dlo + 8);
                uint32_t bl0 = lds32(KL + krow * LDSB + dlo);
                uint32_t bl1 = lds32(KL + krow * LDSB + dlo + 8);
                mma16816(s[nt], ah0, ah1, ah2, ah3, bh0, bh1);
                mma16816(s[nt], al0, al1, al2, al3, bh0, bh1);
                mma16816(s[nt], ah0, ah1, ah2, ah3, bl0, bl1);
            }
        }

        if (kt == qt) {
#pragma unroll
            for (int nt = 0; nt < 8; nt++) {
                int c0 = kt * 64 + nt * 8 + 2 * t;
                if (c0     > rowg)  s[nt][0] = -1e30f;
                if (c0 + 1 > rowg)  s[nt][1] = -1e30f;
                if (c0     > rowg8) s[nt][2] = -1e30f;
                if (c0 + 1 > rowg8) s[nt][3] = -1e30f;
            }
        }

        float tmax0 = -1e30f, tmax1 = -1e30f;
#pragma unroll
        for (int nt = 0; nt < 8; nt++) {
            tmax0 = fmaxf(tmax0, fmaxf(s[nt][0], s[nt][1]));
            tmax1 = fmaxf(tmax1, fmaxf(s[nt][2], s[nt][3]));
        }
        tmax0 = fmaxf(tmax0, __shfl_xor_sync(0xffffffff, tmax0, 1));
        tmax0 = fmaxf(tmax0, __shfl_xor_sync(0xffffffff, tmax0, 2));
        tmax1 = fmaxf(tmax1, __shfl_xor_sync(0xffffffff, tmax1, 1));
        tmax1 = fmaxf(tmax1, __shfl_xor_sync(0xffffffff, tmax1, 2));

        float mnew0 = fmaxf(m0, tmax0);
        float mnew1 = fmaxf(m1, tmax1);
        float f0 = fexp2((m0 - mnew0) * LOG2E);
        float f1 = fexp2((m1 - mnew1) * LOG2E);

        uint32_t pah[4][4], pal[4][4];
        float ls0 = 0.f, ls1 = 0.f;
#pragma unroll
        for (int kc = 0; kc < 4; kc++) {
            float p00 = fexp2((s[2*kc][0]   - mnew0) * LOG2E);
            float p01 = fexp2((s[2*kc][1]   - mnew0) * LOG2E);
            float p02 = fexp2((s[2*kc][2]   - mnew1) * LOG2E);
            float p03 = fexp2((s[2*kc][3]   - mnew1) * LOG2E);
            float p10 = fexp2((s[2*kc+1][0] - mnew0) * LOG2E);
            float p11 = fexp2((s[2*kc+1][1] - mnew0) * LOG2E);
            float p12 = fexp2((s[2*kc+1][2] - mnew1) * LOG2E);
            float p13 = fexp2((s[2*kc+1][3] - mnew1) * LOG2E);
            packsplit(p00, p01, pah[kc][0], pal[kc][0]);
            packsplit(p02, p03, pah[kc][1], pal[kc][1]);
            packsplit(p10, p11, pah[kc][2], pal[kc][2]);
            packsplit(p12, p13, pah[kc][3], pal[kc][3]);
            ls0 += (p00 + p01) + (p10 + p11);
            ls1 += (p02 + p03) + (p12 + p13);
        }
        ls0 += __shfl_xor_sync(0xffffffff, ls0, 1);
        ls0 += __shfl_xor_sync(0xffffffff, ls0, 2);
        ls1 += __shfl_xor_sync(0xffffffff, ls1, 1);
        ls1 += __shfl_xor_sync(0xffffffff, ls1, 2);

        l0 = l0 * f0 + ls0;  m0 = mnew0;
        l1 = l1 * f1 + ls1;  m1 = mnew1;

#pragma unroll
        for (int nt = 0; nt < 8; nt++) {
            o[nt][0] *= f0; o[nt][1] *= f0;
            o[nt][2] *= f1; o[nt][3] *= f1;
        }

#pragma unroll
        for (int kc = 0; kc < 4; kc++) {
            const int klo = kc * 16 + 2 * t;
#pragma unroll
            for (int nt = 0; nt < 8; nt++) {
                const int drow = nt * 8 + g;
                uint32_t vh0 = lds32(VTH + drow * LDSB + klo);
                uint32_t vh1 = lds32(VTH + drow * LDSB + klo + 8);
                uint32_t vl0 = lds32(VTL + drow * LDSB + klo);
                uint32_t vl1 = lds32(VTL + drow * LDSB + klo + 8);
                mma16816(o[nt], pah[kc][0], pah[kc][1], pah[kc][2], pah[kc][3], vh0, vh1);
                mma16816(o[nt], pal[kc][0], pal[kc][1], pal[kc][2], pal[kc][3], vh0, vh1);
                mma16816(o[nt], pah[kc][0], pah[kc][1], pah[kc][2], pah[kc][3], vl0, vl1);
            }
        }
    }

    // ---- epilogue: normalize, split to bf16 hi/lo, write g_yh/g_yl [B,T,C] ----
    {
        float inv0 = 1.0f / l0;
        float inv1 = 1.0f / l1;
        int b = bh / NH, h = bh % NH;
        size_t off0 = ((size_t)(b * TT + rowg))  * DM + h * DH;
        size_t off1 = ((size_t)(b * TT + rowg8)) * DM + h * DH;
#pragma unroll
        for (int nt = 0; nt < 8; nt++) {
            int d = nt * 8 + 2 * t;
            uint32_t hi, lo;
            packsplit(o[nt][0] * inv0, o[nt][1] * inv0, hi, lo);
            *(uint32_t*)(g_yh + off0 + d) = hi;
            *(uint32_t*)(g_yl + off0 + d) = lo;
            packsplit(o[nt][2] * inv1, o[nt][3] * inv1, hi, lo);
            *(uint32_t*)(g_yh + off1 + d) = hi;
            *(uint32_t*)(g_yl + off1 + d) = lo;
        }
    }
}

// ---------------- launch -----------------------------------------------------------
extern "C" void kernel_launch(void* const* d_in, const int* in_sizes, int n_in,
                              void* d_out, int out_size)
{
    const float *x = nullptr, *wa = nullptr, *ba = nullptr, *wp = nullptr, *bp = nullptr;
    for (int divi = 0; divi < 2; divi++) {
        long long div = (divi == 0) ? 1 : 4;
        const float *tx=nullptr,*twa=nullptr,*tba=nullptr,*twp=nullptr,*tbp=nullptr;
        for (int i = 0; i < n_in; i++) {
            long long s = (long long)in_sizes[i] / div;
            if      (s == 3145728) tx  = (const float*)d_in[i];
            else if (s == 1769472) twa = (const float*)d_in[i];
            else if (s == 589824)  twp = (const float*)d_in[i];
            else if (s == 2304)    tba = (const float*)d_in[i];
            else if (s == 768)     tbp = (const float*)d_in[i];
        }
        if (tx && twa && tba && twp && tbp) { x=tx; wa=twa; ba=tba; wp=twp; bp=tbp; break; }
    }
    if (!(x && wa && ba && wp && bp)) return;

    float* out = (float*)d_out;

    cudaFuncSetAttribute(attn_reg, cudaFuncAttributeMaxDynamicSharedMemorySize, ATT_SMEM);

    // 0) split inputs to bf16 hi/lo (weights also transposed)
    split_x<<<MROWS * DM / (256 * 8), 256>>>(x);
    {
        dim3 gw(NQKV / 32, DM / 32);   // (72, 24)
        splitT_w<0><<<gw, 256>>>(wa, NQKV);
        dim3 gp(DM / 32, DM / 32);     // (24, 24)
        splitT_w<1><<<gp, 256>>>(wp, DM);
    }
    // 1) QKV projection (3-term bf16) -> split q/k/v buffers
    {
        dim3 grid(NQKV / GN, MROWS / GM);   // (36, 32)
        gemm_bf<1><<<grid, 256>>>(ba, nullptr, NQKV);
    }
    // 2) causal attention (register-resident mma) -> g_yh/g_yl
    {
        dim3 grid(TT / 64, BB * NH);        // (32, 24)
        attn_reg<<<grid, 128, ATT_SMEM>>>();
    }
    // 3) output projection (3-term bf16)
    {
        dim3 grid(DM / GN, MROWS / GM);     // (12, 32)
        gemm_bf<2><<<grid, 256>>>(bp, out, DM);
    }
}

// round 13
// speedup vs baseline: 4.2288x; 1.3237x over previous
#include <cuda_runtime.h>
#include <cuda_fp16.h>
#include <cstdint>

#define BB 2
#define TT 2048
#define NH 12
#define DH 64
#define DM 768
#define NQKV (3*DM)
#define MROWS (BB*TT)   // 4096

// Scratch (allocation-free). NOTE: never pass these symbols from host code —
// GB300 ATS silently resolves the host shadow address (reads zeros).
__device__ __align__(16) __half g_xh [(size_t)MROWS*DM];
__device__ __align__(16) __half g_xl [(size_t)MROWS*DM];
__device__ __align__(16) __half g_wat[(size_t)NQKV*DM];   // [2304,768] transposed, f16
__device__ __align__(16) __half g_wpt[(size_t)DM*DM];     // [768,768]  transposed, f16
__device__ __align__(16) __half g_qh[(size_t)BB*NH*TT*DH];  // q hi (scaled)
__device__ __align__(16) __half g_ql[(size_t)BB*NH*TT*DH];  // q lo
__device__ __align__(16) __half g_k [(size_t)BB*NH*TT*DH];  // k single f16
__device__ __align__(16) __half g_vt[(size_t)BB*NH*DH*TT];  // v single f16 [B,H,D,T]
__device__ __align__(16) __half g_yh[(size_t)MROWS*DM];
__device__ __align__(16) __half g_yl[(size_t)MROWS*DM];

// ---------------- helpers ----------------------------------------------------------
__device__ __forceinline__ void split_h(float v, __half& hi, __half& lo)
{
    hi = __float2half_rn(v);
    lo = __float2half_rn(v - __half2float(hi));
}

__device__ __forceinline__ void mma16816h(float* c, uint32_t a0, uint32_t a1,
                                          uint32_t a2, uint32_t a3,
                                          uint32_t b0, uint32_t b1)
{
    asm volatile(
        "mma.sync.aligned.m16n8k16.row.col.f32.f16.f16.f32 "
        "{%0,%1,%2,%3}, {%4,%5,%6,%7}, {%8,%9}, {%0,%1,%2,%3};\n"
        : "+f"(c[0]), "+f"(c[1]), "+f"(c[2]), "+f"(c[3])
        : "r"(a0), "r"(a1), "r"(a2), "r"(a3), "r"(b0), "r"(b1));
}

__device__ __forceinline__ uint32_t lds32(const __half* p)
{
    return *(const uint32_t*)p;
}

__device__ __forceinline__ void packsplit_h(float x, float y, uint32_t& hi, uint32_t& lo)
{
    __half2 h = __floats2half2_rn(x, y);
    float2 hf = __half22float2(h);
    __half2 l = __floats2half2_rn(x - hf.x, y - hf.y);
    hi = *(uint32_t*)&h;
    lo = *(uint32_t*)&l;
}

// ---------------- input split kernels ----------------------------------------------
__global__ __launch_bounds__(256) void split_x(const float* __restrict__ x)
{
    size_t i = ((size_t)blockIdx.x * 256 + threadIdx.x) * 8;
    float4 v0 = *(const float4*)(x + i);
    float4 v1 = *(const float4*)(x + i + 4);
    float vv[8] = {v0.x, v0.y, v0.z, v0.w, v1.x, v1.y, v1.z, v1.w};
    __half h[8], l[8];
#pragma unroll
    for (int j = 0; j < 8; j++) split_h(vv[j], h[j], l[j]);
    *(uint4*)(g_xh + i) = *(uint4*)h;
    *(uint4*)(g_xl + i) = *(uint4*)l;
}

// Transpose weight [768, N] -> [N, 768] single f16.  W=0: w_attn, W=1: w_proj
template <int W>
__global__ __launch_bounds__(256) void splitT_w(const float* __restrict__ w, int N)
{
    __shared__ float ts[32][33];
    const int tx = threadIdx.x & 31, ty = threadIdx.x >> 5;  // 32 x 8
    const int n0 = blockIdx.x * 32, k0 = blockIdx.y * 32;
#pragma unroll
    for (int i = 0; i < 4; i++) {
        int ky = ty + i * 8;
        ts[ky][tx] = w[(size_t)(k0 + ky) * N + n0 + tx];
    }
    __syncthreads();
    __half* th = (W == 0) ? g_wat : g_wpt;
#pragma unroll
    for (int i = 0; i < 4; i++) {
        int r = ty + i * 8;
        th[(size_t)(n0 + r) * DM + k0 + tx] = __float2half_rn(ts[tx][r]);
    }
}

// ---------------- 2-term f16 raw-mma GEMM -------------------------------------------
// C[M,N] = A*B^T + bias; A = hi/lo f16 (exact), B = single f16 (transposed [N,K]).
// Tiles: 128x64xK32, 256 threads.
// MODE 1: A = x; epilogue: q -> hi/lo (scaled), k -> single f16, v -> single f16 T.
// MODE 2: A = y; plain fp32 store + bias.
#define GM 128
#define GN 64
#define GKT 32
#define GLD 40
#define GCN 68

template <int MODE>
__global__ __launch_bounds__(256) void gemm_h(const float* __restrict__ bias,
                                              float* __restrict__ Cout, int N)
{
    constexpr int K = DM;
    const __half* __restrict__ Ah = (MODE == 1) ? g_xh : g_yh;
    const __half* __restrict__ Al = (MODE == 1) ? g_xl : g_yl;
    const __half* __restrict__ Bh = (MODE == 1) ? g_wat : g_wpt;

    __shared__ union {
        struct {
            __half AH[GM][GLD], AL[GM][GLD];
            __half BH[GN][GLD];
        } ld;
        float Cs[GM][GCN];
    } sm;

    const int tid  = threadIdx.x;
    const int warp = tid >> 5, lane = tid & 31;
    const int g = lane >> 2, t = lane & 3;
    const int m0 = (warp & 3) * 32, n0 = (warp >> 2) * 32;
    const int bm = blockIdx.y * GM, bn = blockIdx.x * GN;

    float acc[2][4][4] = {};

    for (int k0 = 0; k0 < K; k0 += GKT) {
        __syncthreads();
#pragma unroll
        for (int i = 0; i < 2; i++) {
            int cid = tid + i * 256;
            int r = cid >> 2, c8 = (cid & 3) * 8;
            size_t src = (size_t)(bm + r) * K + k0 + c8;
            *(uint4*)&sm.ld.AH[r][c8] = *(const uint4*)(Ah + src);
            *(uint4*)&sm.ld.AL[r][c8] = *(const uint4*)(Al + src);
        }
        {
            int r = tid >> 2, c8 = (tid & 3) * 8;
            size_t src = (size_t)(bn + r) * K + k0 + c8;
            *(uint4*)&sm.ld.BH[r][c8] = *(const uint4*)(Bh + src);
        }
        __syncthreads();

#pragma unroll
        for (int kc = 0; kc < 2; kc++) {
            const int dlo = kc * 16 + 2 * t;
            uint32_t aH[2][4], aL[2][4];
#pragma unroll
            for (int mi = 0; mi < 2; mi++) {
                int r0 = m0 + mi * 16 + g, r1 = r0 + 8;
                aH[mi][0] = lds32(&sm.ld.AH[r0][dlo]);
                aH[mi][1] = lds32(&sm.ld.AH[r1][dlo]);
                aH[mi][2] = lds32(&sm.ld.AH[r0][dlo + 8]);
                aH[mi][3] = lds32(&sm.ld.AH[r1][dlo + 8]);
                aL[mi][0] = lds32(&sm.ld.AL[r0][dlo]);
                aL[mi][1] = lds32(&sm.ld.AL[r1][dlo]);
                aL[mi][2] = lds32(&sm.ld.AL[r0][dlo + 8]);
                aL[mi][3] = lds32(&sm.ld.AL[r1][dlo + 8]);
            }
#pragma unroll
            for (int ni = 0; ni < 4; ni++) {
                int rn = n0 + ni * 8 + g;
                uint32_t b0 = lds32(&sm.ld.BH[rn][dlo]);
                uint32_t b1 = lds32(&sm.ld.BH[rn][dlo + 8]);
#pragma unroll
                for (int mi = 0; mi < 2; mi++) {
                    mma16816h(acc[mi][ni], aH[mi][0], aH[mi][1], aH[mi][2], aH[mi][3], b0, b1);
                    mma16816h(acc[mi][ni], aL[mi][0], aL[mi][1], aL[mi][2], aL[mi][3], b0, b1);
                }
            }
        }
    }

    __syncthreads();
#pragma unroll
    for (int mi = 0; mi < 2; mi++)
#pragma unroll
        for (int ni = 0; ni < 4; ni++) {
            int r = m0 + mi * 16 + g, c = n0 + ni * 8 + 2 * t;
            *(float2*)&sm.Cs[r][c]     = make_float2(acc[mi][ni][0], acc[mi][ni][1]);
            *(float2*)&sm.Cs[r + 8][c] = make_float2(acc[mi][ni][2], acc[mi][ni][3]);
        }
    __syncthreads();

    if (MODE == 2) {
#pragma unroll
        for (int it = 0; it < 32; it++) {
            int idx = tid + it * 256;
            int r = idx >> 6;
            int n_loc = idx & 63;
            Cout[(size_t)(bm + r) * N + bn + n_loc] = sm.Cs[r][n_loc] + bias[bn + n_loc];
        }
    } else {
        const int which = bn / DM;
        const int hd    = bn % DM;
        const int h     = hd / DH;
        const int b     = bm / TT;
        const int t0    = bm % TT;
        const int bh    = b * NH + h;

        if (which == 2) {
            // V: transposed single-f16 store g_vt[bh][d][t]
#pragma unroll
            for (int it = 0; it < 4; it++) {
                int cid = tid + it * 256;
                int d   = cid >> 4;
                int tc  = (cid & 15) * 8;
                float bval = bias[bn + d];
                __half hb[8];
#pragma unroll
                for (int j = 0; j < 8; j++)
                    hb[j] = __float2half_rn(sm.Cs[tc + j][d] + bval);
                *(uint4*)(g_vt + ((size_t)bh * DH + d) * TT + t0 + tc) = *(uint4*)hb;
            }
        } else if (which == 1) {
            // K: single f16
#pragma unroll
            for (int it = 0; it < 4; it++) {
                int cid = tid + it * 256;
                int r   = cid >> 3;
                int c8  = (cid & 7) * 8;
                __half hb[8];
#pragma unroll
                for (int j = 0; j < 8; j++)
                    hb[j] = __float2half_rn(sm.Cs[r][c8 + j] + bias[bn + c8 + j]);
                *(uint4*)(g_k + ((size_t)bh * TT + t0 + r) * DH + c8) = *(uint4*)hb;
            }
        } else {
            // Q: scaled, split hi/lo
#pragma unroll
            for (int it = 0; it < 4; it++) {
                int cid = tid + it * 256;
                int r   = cid >> 3;
                int c8  = (cid & 7) * 8;
                __half hb[8], lb[8];
#pragma unroll
                for (int j = 0; j < 8; j++) {
                    float v = (sm.Cs[r][c8 + j] + bias[bn + c8 + j]) * 0.125f;
                    split_h(v, hb[j], lb[j]);
                }
                size_t dst = ((size_t)bh * TT + t0 + r) * DH + c8;
                *(uint4*)(g_qh + dst) = *(uint4*)hb;
                *(uint4*)(g_ql + dst) = *(uint4*)lb;
            }
        }
    }
}

// ---------------- Register-resident flash attention (f16 mma) ----------------------
// Q hi/lo (exact, loaded once), K single f16 (rounded), P hi/lo in regs (exact),
// V single f16 (rounded). Per-tile streamed traffic: KH + VT only.
#define LOG2E 1.4426950408889634f
#define LDSB 72

__device__ __forceinline__ float fexp2(float t)   // t <= 0; returns 2^t
{
    t = fmaxf(t, -126.f);
    float fl = floorf(t);
    float x = (t - fl) * 0.69314718056f;
    float p = 1.f + x*(1.f + x*(0.5f + x*(0.16666667f + x*(0.041666667f
              + x*(0.0083333333f + x*0.0013888889f)))));
    return __int_as_float(__float_as_int(p) + ((int)fl << 23));
}

// smem: QH, QL, KH, VT : each 64 x LDSB halves = 9216 B -> 36864 B
#define ATT_SMEM (4*64*LDSB*2)

__global__ __launch_bounds__(128) void attn_reg()
{
    extern __shared__ __half smb[];
    __half* QH = smb;
    __half* QL = QH + 64*LDSB;
    __half* KH = QL + 64*LDSB;
    __half* VT = KH + 64*LDSB;

    const int bh   = blockIdx.y;
    const int qt   = gridDim.x - 1 - blockIdx.x;  // heavy first
    const int tid  = threadIdx.x;
    const int warp = tid >> 5;
    const int lane = tid & 31;
    const int g    = lane >> 2;
    const int t    = lane & 3;
    const int q0   = qt * 64;

    const __half* gqh = g_qh + (size_t)bh * TT * DH;
    const __half* gql = g_ql + (size_t)bh * TT * DH;
    const __half* gk  = g_k  + (size_t)bh * TT * DH;
    const __half* gv  = g_vt + (size_t)bh * DH * TT;

#pragma unroll
    for (int it = 0; it < 4; it++) {
        int cid = tid + it * 128;
        int r   = cid >> 3;
        int c8  = (cid & 7) * 8;
        *(uint4*)(QH + r * LDSB + c8) = *(const uint4*)(gqh + (size_t)(q0 + r) * DH + c8);
        *(uint4*)(QL + r * LDSB + c8) = *(const uint4*)(gql + (size_t)(q0 + r) * DH + c8);
    }

    float o[8][4];
#pragma unroll
    for (int nt = 0; nt < 8; nt++)
#pragma unroll
        for (int e = 0; e < 4; e++) o[nt][e] = 0.f;
    float m0 = -1e30f, m1 = -1e30f, l0 = 0.f, l1 = 0.f;

    const int rowg  = q0 + warp * 16 + g;
    const int rowg8 = rowg + 8;

    for (int kt = 0; kt <= qt; kt++) {
        __syncthreads();
#pragma unroll
        for (int it = 0; it < 4; it++) {
            int cid = tid + it * 128;
            int r   = cid >> 3;
            int c8  = (cid & 7) * 8;
            *(uint4*)(KH + r * LDSB + c8) = *(const uint4*)(gk + (size_t)(kt*64 + r) * DH + c8);
            *(uint4*)(VT + r * LDSB + c8) = *(const uint4*)(gv + (size_t)r * TT + kt*64 + c8);
        }
        __syncthreads();

        // ---- S = Q K^T (Q exact hi/lo, K single f16) ----
        float s[8][4];
#pragma unroll
        for (int nt = 0; nt < 8; nt++)
#pragma unroll
            for (int e = 0; e < 4; e++) s[nt][e] = 0.f;

#pragma unroll
        for (int kc = 0; kc < 4; kc++) {
            const int qrow = warp * 16 + g;
            const int dlo  = kc * 16 + 2 * t;
            uint32_t ah0 = lds32(QH + qrow * LDSB + dlo);
            uint32_t ah1 = lds32(QH + (qrow + 8) * LDSB + dlo);
            uint32_t ah2 = lds32(QH + qrow * LDSB + dlo + 8);
            uint32_t ah3 = lds32(QH + (qrow + 8) * LDSB + dlo + 8);
            uint32_t al0 = lds32(QL + qrow * LDSB + dlo);
            uint32_t al1 = lds32(QL + (qrow + 8) * LDSB + dlo);
            uint32_t al2 = lds32(QL + qrow * LDSB + dlo + 8);
            uint32_t al3 = lds32(QL + (qrow + 8) * LDSB + dlo + 8);
#pragma unroll
            for (int nt = 0; nt < 8; nt++) {
                const int krow = nt * 8 + g;
                uint32_t b0 = lds32(KH + krow * LDSB + dlo);
                uint32_t b1 = lds32(KH + krow * LDSB + dlo + 8);
                mma16816h(s[nt], ah0, ah1, ah2, ah3, b0, b1);
                mma16816h(s[nt], al0, al1, al2, al3, b0, b1);
            }
        }

        // ---- causal mask on the diagonal tile ----
        if (kt == qt) {
#pragma unroll
            for (int nt = 0; nt < 8; nt++) {
                int c0 = kt * 64 + nt * 8 + 2 * t;
                if (c0     > rowg)  s[nt][0] = -1e30f;
                if (c0 + 1 > rowg)  s[nt][1] = -1e30f;
                if (c0     > rowg8) s[nt][2] = -1e30f;
                if (c0 + 1 > rowg8) s[nt][3] = -1e30f;
            }
        }

        // ---- online softmax ----
        float tmax0 = -1e30f, tmax1 = -1e30f;
#pragma unroll
        for (int nt = 0; nt < 8; nt++) {
            tmax0 = fmaxf(tmax0, fmaxf(s[nt][0], s[nt][1]));
            tmax1 = fmaxf(tmax1, fmaxf(s[nt][2], s[nt][3]));
        }
        tmax0 = fmaxf(tmax0, __shfl_xor_sync(0xffffffff, tmax0, 1));
        tmax0 = fmaxf(tmax0, __shfl_xor_sync(0xffffffff, tmax0, 2));
        tmax1 = fmaxf(tmax1, __shfl_xor_sync(0xffffffff, tmax1, 1));
        tmax1 = fmaxf(tmax1, __shfl_xor_sync(0xffffffff, tmax1, 2));

        float mnew0 = fmaxf(m0, tmax0);
        float mnew1 = fmaxf(m1, tmax1);
        float f0 = fexp2((m0 - mnew0) * LOG2E);
        float f1 = fexp2((m1 - mnew1) * LOG2E);

        uint32_t pah[4][4], pal[4][4];
        float ls0 = 0.f, ls1 = 0.f;
#pragma unroll
        for (int kc = 0; kc < 4; kc++) {
            float p00 = fexp2((s[2*kc][0]   - mnew0) * LOG2E);
            float p01 = fexp2((s[2*kc][1]   - mnew0) * LOG2E);
            float p02 = fexp2((s[2*kc][2]   - mnew1) * LOG2E);
            float p03 = fexp2((s[2*kc][3]   - mnew1) * LOG2E);
            float p10 = fexp2((s[2*kc+1][0] - mnew0) * LOG2E);
            float p11 = fexp2((s[2*kc+1][1] - mnew0) * LOG2E);
            float p12 = fexp2((s[2*kc+1][2] - mnew1) * LOG2E);
            float p13 = fexp2((s[2*kc+1][3] - mnew1) * LOG2E);
            packsplit_h(p00, p01, pah[kc][0], pal[kc][0]);
            packsplit_h(p02, p03, pah[kc][1], pal[kc][1]);
            packsplit_h(p10, p11, pah[kc][2], pal[kc][2]);
            packsplit_h(p12, p13, pah[kc][3], pal[kc][3]);
            ls0 += (p00 + p01) + (p10 + p11);
            ls1 += (p02 + p03) + (p12 + p13);
        }
        ls0 += __shfl_xor_sync(0xffffffff, ls0, 1);
        ls0 += __shfl_xor_sync(0xffffffff, ls0, 2);
        ls1 += __shfl_xor_sync(0xffffffff, ls1, 1);
        ls1 += __shfl_xor_sync(0xffffffff, ls1, 2);

        l0 = l0 * f0 + ls0;  m0 = mnew0;
        l1 = l1 * f1 + ls1;  m1 = mnew1;

#pragma unroll
        for (int nt = 0; nt < 8; nt++) {
            o[nt][0] *= f0; o[nt][1] *= f0;
            o[nt][2] *= f1; o[nt][3] *= f1;
        }

        // ---- O += P * V (P exact hi/lo, V single f16) ----
#pragma unroll
        for (int kc = 0; kc < 4; kc++) {
            const int klo = kc * 16 + 2 * t;
#pragma unroll
            for (int nt = 0; nt < 8; nt++) {
                const int drow = nt * 8 + g;
                uint32_t v0 = lds32(VT + drow * LDSB + klo);
                uint32_t v1 = lds32(VT + drow * LDSB + klo + 8);
                mma16816h(o[nt], pah[kc][0], pah[kc][1], pah[kc][2], pah[kc][3], v0, v1);
                mma16816h(o[nt], pal[kc][0], pal[kc][1], pal[kc][2], pal[kc][3], v0, v1);
            }
        }
    }

    // ---- epilogue: normalize, split f16 hi/lo, write g_yh/g_yl ----
    {
        float inv0 = 1.0f / l0;
        float inv1 = 1.0f / l1;
        int b = bh / NH, h = bh % NH;
        size_t off0 = ((size_t)(b * TT + rowg))  * DM + h * DH;
        size_t off1 = ((size_t)(b * TT + rowg8)) * DM + h * DH;
#pragma unroll
        for (int nt = 0; nt < 8; nt++) {
            int d = nt * 8 + 2 * t;
            uint32_t hi, lo;
            packsplit_h(o[nt][0] * inv0, o[nt][1] * inv0, hi, lo);
            *(uint32_t*)(g_yh + off0 + d) = hi;
            *(uint32_t*)(g_yl + off0 + d) = lo;
            packsplit_h(o[nt][2] * inv1, o[nt][3] * inv1, hi, lo);
            *(uint32_t*)(g_yh + off1 + d) = hi;
            *(uint32_t*)(g_yl + off1 + d) = lo;
        }
    }
}

// ---------------- launch -----------------------------------------------------------
extern "C" void kernel_launch(void* const* d_in, const int* in_sizes, int n_in,
                              void* d_out, int out_size)
{
    const float *x = nullptr, *wa = nullptr, *ba = nullptr, *wp = nullptr, *bp = nullptr;
    for (int divi = 0; divi < 2; divi++) {
        long long div = (divi == 0) ? 1 : 4;
        const float *tx=nullptr,*twa=nullptr,*tba=nullptr,*twp=nullptr,*tbp=nullptr;
        for (int i = 0; i < n_in; i++) {
            long long s = (long long)in_sizes[i] / div;
            if      (s == 3145728) tx  = (const float*)d_in[i];
            else if (s == 1769472) twa = (const float*)d_in[i];
            else if (s == 589824)  twp = (const float*)d_in[i];
            else if (s == 2304)    tba = (const float*)d_in[i];
            else if (s == 768)     tbp = (const float*)d_in[i];
        }
        if (tx && twa && tba && twp && tbp) { x=tx; wa=twa; ba=tba; wp=twp; bp=tbp; break; }
    }
    if (!(x && wa && ba && wp && bp)) return;

    float* out = (float*)d_out;

    cudaFuncSetAttribute(attn_reg, cudaFuncAttributeMaxDynamicSharedMemorySize, ATT_SMEM);

    // 0) split x to f16 hi/lo; transpose weights to single f16
    split_x<<<MROWS * DM / (256 * 8), 256>>>(x);
    {
        dim3 gw(NQKV / 32, DM / 32);   // (72, 24)
        splitT_w<0><<<gw, 256>>>(wa, NQKV);
        dim3 gp(DM / 32, DM / 32);     // (24, 24)
        splitT_w<1><<<gp, 256>>>(wp, DM);
    }
    // 1) QKV projection (2-term f16) -> q hi/lo, k f16, v f16 transposed
    {
        dim3 grid(NQKV / GN, MROWS / GM);   // (36, 32)
        gemm_h<1><<<grid, 256>>>(ba, nullptr, NQKV);
    }
    // 2) causal attention -> g_yh/g_yl
    {
        dim3 grid(TT / 64, BB * NH);        // (32, 24)
        attn_reg<<<grid, 128, ATT_SMEM>>>();
    }
    // 3) output projection (2-term f16)
    {
        dim3 grid(DM / GN, MROWS / GM);     // (12, 32)
        gemm_h<2><<<grid, 256>>>(bp, out, DM);
    }
}

// round 14
// speedup vs baseline: 4.4394x; 1.0498x over previous
#include <cuda_runtime.h>
#include <cuda_fp16.h>
#include <cstdint>

#define BB 2
#define TT 2048
#define NH 12
#define DH 64
#define DM 768
#define NQKV (3*DM)
#define MROWS (BB*TT)   // 4096

// Scratch (allocation-free). NOTE: never pass these symbols from host code —
// GB300 ATS silently resolves the host shadow address (reads zeros).
__device__ __align__(16) __half g_xh [(size_t)MROWS*DM];
__device__ __align__(16) __half g_xl [(size_t)MROWS*DM];
__device__ __align__(16) __half g_wat[(size_t)NQKV*DM];   // [2304,768] transposed, f16
__device__ __align__(16) __half g_wpt[(size_t)DM*DM];     // [768,768]  transposed, f16
__device__ __align__(16) __half g_qh[(size_t)BB*NH*TT*DH];  // q hi (scaled)
__device__ __align__(16) __half g_ql[(size_t)BB*NH*TT*DH];  // q lo
__device__ __align__(16) __half g_k [(size_t)BB*NH*TT*DH];  // k single f16
__device__ __align__(16) __half g_vt[(size_t)BB*NH*DH*TT];  // v single f16 [B,H,D,T]
__device__ __align__(16) __half g_yh[(size_t)MROWS*DM];
__device__ __align__(16) __half g_yl[(size_t)MROWS*DM];

// ---------------- helpers ----------------------------------------------------------
__device__ __forceinline__ void split_h(float v, __half& hi, __half& lo)
{
    hi = __float2half_rn(v);
    lo = __float2half_rn(v - __half2float(hi));
}

__device__ __forceinline__ void mma16816h(float* c, uint32_t a0, uint32_t a1,
                                          uint32_t a2, uint32_t a3,
                                          uint32_t b0, uint32_t b1)
{
    asm volatile(
        "mma.sync.aligned.m16n8k16.row.col.f32.f16.f16.f32 "
        "{%0,%1,%2,%3}, {%4,%5,%6,%7}, {%8,%9}, {%0,%1,%2,%3};\n"
        : "+f"(c[0]), "+f"(c[1]), "+f"(c[2]), "+f"(c[3])
        : "r"(a0), "r"(a1), "r"(a2), "r"(a3), "r"(b0), "r"(b1));
}

__device__ __forceinline__ uint32_t lds32(const __half* p)
{
    return *(const uint32_t*)p;
}

__device__ __forceinline__ void packsplit_h(float x, float y, uint32_t& hi, uint32_t& lo)
{
    __half2 h = __floats2half2_rn(x, y);
    float2 hf = __half22float2(h);
    __half2 l = __floats2half2_rn(x - hf.x, y - hf.y);
    hi = *(uint32_t*)&h;
    lo = *(uint32_t*)&l;
}

// ---------------- input split kernels ----------------------------------------------
__global__ __launch_bounds__(256) void split_x(const float* __restrict__ x)
{
    size_t i = ((size_t)blockIdx.x * 256 + threadIdx.x) * 8;
    float4 v0 = *(const float4*)(x + i);
    float4 v1 = *(const float4*)(x + i + 4);
    float vv[8] = {v0.x, v0.y, v0.z, v0.w, v1.x, v1.y, v1.z, v1.w};
    __half h[8], l[8];
#pragma unroll
    for (int j = 0; j < 8; j++) split_h(vv[j], h[j], l[j]);
    *(uint4*)(g_xh + i) = *(uint4*)h;
    *(uint4*)(g_xl + i) = *(uint4*)l;
}

// Transpose weight [768, N] -> [N, 768] single f16.  W=0: w_attn, W=1: w_proj
template <int W>
__global__ __launch_bounds__(256) void splitT_w(const float* __restrict__ w, int N)
{
    __shared__ float ts[32][33];
    const int tx = threadIdx.x & 31, ty = threadIdx.x >> 5;  // 32 x 8
    const int n0 = blockIdx.x * 32, k0 = blockIdx.y * 32;
#pragma unroll
    for (int i = 0; i < 4; i++) {
        int ky = ty + i * 8;
        ts[ky][tx] = w[(size_t)(k0 + ky) * N + n0 + tx];
    }
    __syncthreads();
    __half* th = (W == 0) ? g_wat : g_wpt;
#pragma unroll
    for (int i = 0; i < 4; i++) {
        int r = ty + i * 8;
        th[(size_t)(n0 + r) * DM + k0 + tx] = __float2half_rn(ts[tx][r]);
    }
}

// ---------------- 2-term f16 raw-mma GEMM -------------------------------------------
// C[M,N] = A*B^T + bias; A = hi/lo f16 (exact), B = single f16 (transposed [N,K]).
// Block tile 128x128xK32, 256 threads (8 warps, 4m x 2n, warp tile 32x64).
// MODE 1: A = x; epilogue: q -> hi/lo (scaled), k -> f16, v -> f16 transposed.
// MODE 2: A = y; plain fp32 store + bias.
#define GM 128
#define GN 128
#define GKT 32
#define GLD 40
#define GCN 68

template <int MODE>
__global__ __launch_bounds__(256) void gemm_h(const float* __restrict__ bias,
                                              float* __restrict__ Cout, int N)
{
    constexpr int K = DM;
    const __half* __restrict__ Ah = (MODE == 1) ? g_xh : g_yh;
    const __half* __restrict__ Al = (MODE == 1) ? g_xl : g_yl;
    const __half* __restrict__ Bh = (MODE == 1) ? g_wat : g_wpt;

    __shared__ union {
        struct {
            __half AH[GM][GLD], AL[GM][GLD];
            __half BH[GN][GLD];
        } ld;                         // 30720 B
        float Cs[GM][GCN];            // 34816 B
    } sm;

    const int tid  = threadIdx.x;
    const int warp = tid >> 5, lane = tid & 31;
    const int g = lane >> 2, t = lane & 3;
    const int m0 = (warp & 3) * 32, wn = warp >> 2, n0 = wn * 64;
    const int bm = blockIdx.y * GM, bn = blockIdx.x * GN;

    float acc[2][8][4] = {};

    for (int k0 = 0; k0 < K; k0 += GKT) {
        __syncthreads();
#pragma unroll
        for (int i = 0; i < 2; i++) {
            int cid = tid + i * 256;
            int r = cid >> 2, c8 = (cid & 3) * 8;
            size_t src = (size_t)(bm + r) * K + k0 + c8;
            *(uint4*)&sm.ld.AH[r][c8] = *(const uint4*)(Ah + src);
            *(uint4*)&sm.ld.AL[r][c8] = *(const uint4*)(Al + src);
        }
#pragma unroll
        for (int i = 0; i < 2; i++) {
            int cid = tid + i * 256;
            int r = cid >> 2, c8 = (cid & 3) * 8;
            *(uint4*)&sm.ld.BH[r][c8] = *(const uint4*)(Bh + (size_t)(bn + r) * K + k0 + c8);
        }
        __syncthreads();

#pragma unroll
        for (int kc = 0; kc < 2; kc++) {
            const int dlo = kc * 16 + 2 * t;
            uint32_t aH[2][4], aL[2][4];
#pragma unroll
            for (int mi = 0; mi < 2; mi++) {
                int r0 = m0 + mi * 16 + g, r1 = r0 + 8;
                aH[mi][0] = lds32(&sm.ld.AH[r0][dlo]);
                aH[mi][1] = lds32(&sm.ld.AH[r1][dlo]);
                aH[mi][2] = lds32(&sm.ld.AH[r0][dlo + 8]);
                aH[mi][3] = lds32(&sm.ld.AH[r1][dlo + 8]);
                aL[mi][0] = lds32(&sm.ld.AL[r0][dlo]);
                aL[mi][1] = lds32(&sm.ld.AL[r1][dlo]);
                aL[mi][2] = lds32(&sm.ld.AL[r0][dlo + 8]);
                aL[mi][3] = lds32(&sm.ld.AL[r1][dlo + 8]);
            }
#pragma unroll
            for (int ni = 0; ni < 8; ni++) {
                int rn = n0 + ni * 8 + g;
                uint32_t b0 = lds32(&sm.ld.BH[rn][dlo]);
                uint32_t b1 = lds32(&sm.ld.BH[rn][dlo + 8]);
#pragma unroll
                for (int mi = 0; mi < 2; mi++) {
                    mma16816h(acc[mi][ni], aH[mi][0], aH[mi][1], aH[mi][2], aH[mi][3], b0, b1);
                    mma16816h(acc[mi][ni], aL[mi][0], aL[mi][1], aL[mi][2], aL[mi][3], b0, b1);
                }
            }
        }
    }

    // Epilogue: two 64-col passes through Cs (warps partition cols by wn)
#pragma unroll
    for (int pass = 0; pass < 2; pass++) {
        __syncthreads();
        if (wn == pass) {
#pragma unroll
            for (int mi = 0; mi < 2; mi++)
#pragma unroll
                for (int ni = 0; ni < 8; ni++) {
                    int r = m0 + mi * 16 + g, c = ni * 8 + 2 * t;
                    *(float2*)&sm.Cs[r][c]     = make_float2(acc[mi][ni][0], acc[mi][ni][1]);
                    *(float2*)&sm.Cs[r + 8][c] = make_float2(acc[mi][ni][2], acc[mi][ni][3]);
                }
        }
        __syncthreads();

        const int nwin = bn + pass * 64;   // 64-aligned window
        if (MODE == 2) {
#pragma unroll
            for (int it = 0; it < 32; it++) {
                int idx = tid + it * 256;
                int r = idx >> 6;
                int n_loc = idx & 63;
                Cout[(size_t)(bm + r) * N + nwin + n_loc] = sm.Cs[r][n_loc] + bias[nwin + n_loc];
            }
        } else {
            const int which = nwin / DM;
            const int hd    = nwin % DM;
            const int h     = hd / DH;
            const int b     = bm / TT;
            const int t0    = bm % TT;
            const int bh    = b * NH + h;

            if (which == 2) {
#pragma unroll
                for (int it = 0; it < 4; it++) {
                    int cid = tid + it * 256;
                    int d   = cid >> 4;
                    int tc  = (cid & 15) * 8;
                    float bval = bias[nwin + d];
                    __half hb[8];
#pragma unroll
                    for (int j = 0; j < 8; j++)
                        hb[j] = __float2half_rn(sm.Cs[tc + j][d] + bval);
                    *(uint4*)(g_vt + ((size_t)bh * DH + d) * TT + t0 + tc) = *(uint4*)hb;
                }
            } else if (which == 1) {
#pragma unroll
                for (int it = 0; it < 4; it++) {
                    int cid = tid + it * 256;
                    int r   = cid >> 3;
                    int c8  = (cid & 7) * 8;
                    __half hb[8];
#pragma unroll
                    for (int j = 0; j < 8; j++)
                        hb[j] = __float2half_rn(sm.Cs[r][c8 + j] + bias[nwin + c8 + j]);
                    *(uint4*)(g_k + ((size_t)bh * TT + t0 + r) * DH + c8) = *(uint4*)hb;
                }
            } else {
#pragma unroll
                for (int it = 0; it < 4; it++) {
                    int cid = tid + it * 256;
                    int r   = cid >> 3;
                    int c8  = (cid & 7) * 8;
                    __half hb[8], lb[8];
#pragma unroll
                    for (int j = 0; j < 8; j++) {
                        float v = (sm.Cs[r][c8 + j] + bias[nwin + c8 + j]) * 0.125f;
                        split_h(v, hb[j], lb[j]);
                    }
                    size_t dst = ((size_t)bh * TT + t0 + r) * DH + c8;
                    *(uint4*)(g_qh + dst) = *(uint4*)hb;
                    *(uint4*)(g_ql + dst) = *(uint4*)lb;
                }
            }
        }
    }
}

// ---------------- Register-resident flash attention (f16 mma) ----------------------
// Q fragments hoisted to registers for the whole block; per-tile traffic K + V only.
#define LOG2E 1.4426950408889634f
#define LDSB 72

__device__ __forceinline__ float fexp2(float t)   // t <= 0; returns 2^t
{
    t = fmaxf(t, -126.f);
    float fl = floorf(t);
    float x = (t - fl) * 0.69314718056f;
    float p = 1.f + x*(1.f + x*(0.5f + x*(0.16666667f + x*(0.041666667f
              + x*(0.0083333333f + x*0.0013888889f)))));
    return __int_as_float(__float_as_int(p) + ((int)fl << 23));
}

// smem: QH, QL, KH, VT : each 64 x LDSB halves = 9216 B -> 36864 B
#define ATT_SMEM (4*64*LDSB*2)

__global__ __launch_bounds__(128) void attn_reg()
{
    extern __shared__ __half smb[];
    __half* QH = smb;
    __half* QL = QH + 64*LDSB;
    __half* KH = QL + 64*LDSB;
    __half* VT = KH + 64*LDSB;

    const int bh   = blockIdx.y;
    const int qt   = gridDim.x - 1 - blockIdx.x;  // heavy first
    const int tid  = threadIdx.x;
    const int warp = tid >> 5;
    const int lane = tid & 31;
    const int g    = lane >> 2;
    const int t    = lane & 3;
    const int q0   = qt * 64;

    const __half* gqh = g_qh + (size_t)bh * TT * DH;
    const __half* gql = g_ql + (size_t)bh * TT * DH;
    const __half* gk  = g_k  + (size_t)bh * TT * DH;
    const __half* gv  = g_vt + (size_t)bh * DH * TT;

#pragma unroll
    for (int it = 0; it < 4; it++) {
        int cid = tid + it * 128;
        int r   = cid >> 3;
        int c8  = (cid & 7) * 8;
        *(uint4*)(QH + r * LDSB + c8) = *(const uint4*)(gqh + (size_t)(q0 + r) * DH + c8);
        *(uint4*)(QL + r * LDSB + c8) = *(const uint4*)(gql + (size_t)(q0 + r) * DH + c8);
    }
    __syncthreads();

    // Hoist Q fragments into registers (block-invariant across kt)
    uint32_t qfh[4][4], qfl[4][4];
    {
        const int qrow = warp * 16 + g;
#pragma unroll
        for (int kc = 0; kc < 4; kc++) {
            const int dlo = kc * 16 + 2 * t;
            qfh[kc][0] = lds32(QH + qrow * LDSB + dlo);
            qfh[kc][1] = lds32(QH + (qrow + 8) * LDSB + dlo);
            qfh[kc][2] = lds32(QH + qrow * LDSB + dlo + 8);
            qfh[kc][3] = lds32(QH + (qrow + 8) * LDSB + dlo + 8);
            qfl[kc][0] = lds32(QL + qrow * LDSB + dlo);
            qfl[kc][1] = lds32(QL + (qrow + 8) * LDSB + dlo);
            qfl[kc][2] = lds32(QL + qrow * LDSB + dlo + 8);
            qfl[kc][3] = lds32(QL + (qrow + 8) * LDSB + dlo + 8);
        }
    }

    float o[8][4];
#pragma unroll
    for (int nt = 0; nt < 8; nt++)
#pragma unroll
        for (int e = 0; e < 4; e++) o[nt][e] = 0.f;
    float m0 = -1e30f, m1 = -1e30f, l0 = 0.f, l1 = 0.f;

    const int rowg  = q0 + warp * 16 + g;
    const int rowg8 = rowg + 8;

    for (int kt = 0; kt <= qt; kt++) {
        __syncthreads();
#pragma unroll
        for (int it = 0; it < 4; it++) {
            int cid = tid + it * 128;
            int r   = cid >> 3;
            int c8  = (cid & 7) * 8;
            *(uint4*)(KH + r * LDSB + c8) = *(const uint4*)(gk + (size_t)(kt*64 + r) * DH + c8);
            *(uint4*)(VT + r * LDSB + c8) = *(const uint4*)(gv + (size_t)r * TT + kt*64 + c8);
        }
        __syncthreads();

        // ---- S = Q K^T ----
        float s[8][4];
#pragma unroll
        for (int nt = 0; nt < 8; nt++)
#pragma unroll
            for (int e = 0; e < 4; e++) s[nt][e] = 0.f;

#pragma unroll
        for (int kc = 0; kc < 4; kc++) {
            const int dlo = kc * 16 + 2 * t;
#pragma unroll
            for (int nt = 0; nt < 8; nt++) {
                const int krow = nt * 8 + g;
                uint32_t b0 = lds32(KH + krow * LDSB + dlo);
                uint32_t b1 = lds32(KH + krow * LDSB + dlo + 8);
                mma16816h(s[nt], qfh[kc][0], qfh[kc][1], qfh[kc][2], qfh[kc][3], b0, b1);
                mma16816h(s[nt], qfl[kc][0], qfl[kc][1], qfl[kc][2], qfl[kc][3], b0, b1);
            }
        }

        // ---- causal mask on the diagonal tile ----
        if (kt == qt) {
#pragma unroll
            for (int nt = 0; nt < 8; nt++) {
                int c0 = kt * 64 + nt * 8 + 2 * t;
                if (c0     > rowg)  s[nt][0] = -1e30f;
                if (c0 + 1 > rowg)  s[nt][1] = -1e30f;
                if (c0     > rowg8) s[nt][2] = -1e30f;
                if (c0 + 1 > rowg8) s[nt][3] = -1e30f;
            }
        }

        // ---- online softmax ----
        float tmax0 = -1e30f, tmax1 = -1e30f;
#pragma unroll
        for (int nt = 0; nt < 8; nt++) {
            tmax0 = fmaxf(tmax0, fmaxf(s[nt][0], s[nt][1]));
            tmax1 = fmaxf(tmax1, fmaxf(s[nt][2], s[nt][3]));
        }
        tmax0 = fmaxf(tmax0, __shfl_xor_sync(0xffffffff, tmax0, 1));
        tmax0 = fmaxf(tmax0, __shfl_xor_sync(0xffffffff, tmax0, 2));
        tmax1 = fmaxf(tmax1, __shfl_xor_sync(0xffffffff, tmax1, 1));
        tmax1 = fmaxf(tmax1, __shfl_xor_sync(0xffffffff, tmax1, 2));

        float mnew0 = fmaxf(m0, tmax0);
        float mnew1 = fmaxf(m1, tmax1);
        float f0 = fexp2((m0 - mnew0) * LOG2E);
        float f1 = fexp2((m1 - mnew1) * LOG2E);

        uint32_t pah[4][4], pal[4][4];
        float ls0 = 0.f, ls1 = 0.f;
#pragma unroll
        for (int kc = 0; kc < 4; kc++) {
            float p00 = fexp2((s[2*kc][0]   - mnew0) * LOG2E);
            float p01 = fexp2((s[2*kc][1]   - mnew0) * LOG2E);
            float p02 = fexp2((s[2*kc][2]   - mnew1) * LOG2E);
            float p03 = fexp2((s[2*kc][3]   - mnew1) * LOG2E);
            float p10 = fexp2((s[2*kc+1][0] - mnew0) * LOG2E);
            float p11 = fexp2((s[2*kc+1][1] - mnew0) * LOG2E);
            float p12 = fexp2((s[2*kc+1][2] - mnew1) * LOG2E);
            float p13 = fexp2((s[2*kc+1][3] - mnew1) * LOG2E);
            packsplit_h(p00, p01, pah[kc][0], pal[kc][0]);
            packsplit_h(p02, p03, pah[kc][1], pal[kc][1]);
            packsplit_h(p10, p11, pah[kc][2], pal[kc][2]);
            packsplit_h(p12, p13, pah[kc][3], pal[kc][3]);
            ls0 += (p00 + p01) + (p10 + p11);
            ls1 += (p02 + p03) + (p12 + p13);
        }
        ls0 += __shfl_xor_sync(0xffffffff, ls0, 1);
        ls0 += __shfl_xor_sync(0xffffffff, ls0, 2);
        ls1 += __shfl_xor_sync(0xffffffff, ls1, 1);
        ls1 += __shfl_xor_sync(0xffffffff, ls1, 2);

        l0 = l0 * f0 + ls0;  m0 = mnew0;
        l1 = l1 * f1 + ls1;  m1 = mnew1;

#pragma unroll
        for (int nt = 0; nt < 8; nt++) {
            o[nt][0] *= f0; o[nt][1] *= f0;
            o[nt][2] *= f1; o[nt][3] *= f1;
        }

        // ---- O += P * V (P exact hi/lo, V single f16) ----
#pragma unroll
        for (int kc = 0; kc < 4; kc++) {
            const int klo = kc * 16 + 2 * t;
#pragma unroll
            for (int nt = 0; nt < 8; nt++) {
                const int drow = nt * 8 + g;
                uint32_t v0 = lds32(VT + drow * LDSB + klo);
                uint32_t v1 = lds32(VT + drow * LDSB + klo + 8);
                mma16816h(o[nt], pah[kc][0], pah[kc][1], pah[kc][2], pah[kc][3], v0, v1);
                mma16816h(o[nt], pal[kc][0], pal[kc][1], pal[kc][2], pal[kc][3], v0, v1);
            }
        }
    }

    // ---- epilogue: normalize, split f16 hi/lo, write g_yh/g_yl ----
    {
        float inv0 = 1.0f / l0;
        float inv1 = 1.0f / l1;
        int b = bh / NH, h = bh % NH;
        size_t off0 = ((size_t)(b * TT + rowg))  * DM + h * DH;
        size_t off1 = ((size_t)(b * TT + rowg8)) * DM + h * DH;
#pragma unroll
        for (int nt = 0; nt < 8; nt++) {
            int d = nt * 8 + 2 * t;
            uint32_t hi, lo;
            packsplit_h(o[nt][0] * inv0, o[nt][1] * inv0, hi, lo);
            *(uint32_t*)(g_yh + off0 + d) = hi;
            *(uint32_t*)(g_yl + off0 + d) = lo;
            packsplit_h(o[nt][2] * inv1, o[nt][3] * inv1, hi, lo);
            *(uint32_t*)(g_yh + off1 + d) = hi;
            *(uint32_t*)(g_yl + off1 + d) = lo;
        }
    }
}

// ---------------- launch -----------------------------------------------------------
extern "C" void kernel_launch(void* const* d_in, const int* in_sizes, int n_in,
                              void* d_out, int out_size)
{
    const float *x = nullptr, *wa = nullptr, *ba = nullptr, *wp = nullptr, *bp = nullptr;
    for (int divi = 0; divi < 2; divi++) {
        long long div = (divi == 0) ? 1 : 4;
        const float *tx=nullptr,*twa=nullptr,*tba=nullptr,*twp=nullptr,*tbp=nullptr;
        for (int i = 0; i < n_in; i++) {
            long long s = (long long)in_sizes[i] / div;
            if      (s == 3145728) tx  = (const float*)d_in[i];
            else if (s == 1769472) twa = (const float*)d_in[i];
            else if (s == 589824)  twp = (const float*)d_in[i];
            else if (s == 2304)    tba = (const float*)d_in[i];
            else if (s == 768)     tbp = (const float*)d_in[i];
        }
        if (tx && twa && tba && twp && tbp) { x=tx; wa=twa; ba=tba; wp=twp; bp=tbp; break; }
    }
    if (!(x && wa && ba && wp && bp)) return;

    float* out = (float*)d_out;

    cudaFuncSetAttribute(attn_reg, cudaFuncAttributeMaxDynamicSharedMemorySize, ATT_SMEM);

    // 0) split x to f16 hi/lo; transpose weights to single f16
    split_x<<<MROWS * DM / (256 * 8), 256>>>(x);
    {
        dim3 gw(NQKV / 32, DM / 32);   // (72, 24)
        splitT_w<0><<<gw, 256>>>(wa, NQKV);
        dim3 gp(DM / 32, DM / 32);     // (24, 24)
        splitT_w<1><<<gp, 256>>>(wp, DM);
    }
    // 1) QKV projection (2-term f16) -> q hi/lo, k f16, v f16 transposed
    {
        dim3 grid(NQKV / GN, MROWS / GM);   // (18, 32)
        gemm_h<1><<<grid, 256>>>(ba, nullptr, NQKV);
    }
    // 2) causal attention -> g_yh/g_yl
    {
        dim3 grid(TT / 64, BB * NH);        // (32, 24)
        attn_reg<<<grid, 128, ATT_SMEM>>>();
    }
    // 3) output projection (2-term f16)
    {
        dim3 grid(DM / GN, MROWS / GM);     // (6, 32)
        gemm_h<2><<<grid, 256>>>(bp, out, DM);
    }
}

// round 15
// speedup vs baseline: 4.5694x; 1.0293x over previous
#include <cuda_runtime.h>
#include <cuda_fp16.h>
#include <cstdint>

#define BB 2
#define TT 2048
#define NH 12
#define DH 64
#define DM 768
#define NQKV (3*DM)
#define MROWS (BB*TT)   // 4096

// Scratch (allocation-free). NOTE: never pass these symbols from host code —
// GB300 ATS silently resolves the host shadow address (reads zeros).
__device__ __align__(16) __half g_xh [(size_t)MROWS*DM];
__device__ __align__(16) __half g_xl [(size_t)MROWS*DM];
__device__ __align__(16) __half g_wat[(size_t)NQKV*DM];   // [2304,768] transposed, f16
__device__ __align__(16) __half g_wpt[(size_t)DM*DM];     // [768,768]  transposed, f16
__device__ __align__(16) __half g_qh[(size_t)BB*NH*TT*DH];  // q hi (scaled)
__device__ __align__(16) __half g_ql[(size_t)BB*NH*TT*DH];  // q lo
__device__ __align__(16) __half g_k [(size_t)BB*NH*TT*DH];  // k single f16
__device__ __align__(16) __half g_vt[(size_t)BB*NH*DH*TT];  // v single f16 [B,H,D,T]
__device__ __align__(16) __half g_yh[(size_t)MROWS*DM];
__device__ __align__(16) __half g_yl[(size_t)MROWS*DM];

// ---------------- helpers ----------------------------------------------------------
__device__ __forceinline__ void split_h(float v, __half& hi, __half& lo)
{
    hi = __float2half_rn(v);
    lo = __float2half_rn(v - __half2float(hi));
}

__device__ __forceinline__ void mma16816h(float* c, uint32_t a0, uint32_t a1,
                                          uint32_t a2, uint32_t a3,
                                          uint32_t b0, uint32_t b1)
{
    asm volatile(
        "mma.sync.aligned.m16n8k16.row.col.f32.f16.f16.f32 "
        "{%0,%1,%2,%3}, {%4,%5,%6,%7}, {%8,%9}, {%0,%1,%2,%3};\n"
        : "+f"(c[0]), "+f"(c[1]), "+f"(c[2]), "+f"(c[3])
        : "r"(a0), "r"(a1), "r"(a2), "r"(a3), "r"(b0), "r"(b1));
}

__device__ __forceinline__ uint32_t lds32(const __half* p)
{
    return *(const uint32_t*)p;
}

__device__ __forceinline__ void packsplit_h(float x, float y, uint32_t& hi, uint32_t& lo)
{
    __half2 h = __floats2half2_rn(x, y);
    float2 hf = __half22float2(h);
    __half2 l = __floats2half2_rn(x - hf.x, y - hf.y);
    hi = *(uint32_t*)&h;
    lo = *(uint32_t*)&l;
}

__device__ __forceinline__ void cp16(void* smem_ptr, const void* gptr)
{
    uint32_t sa = (uint32_t)__cvta_generic_to_shared(smem_ptr);
    asm volatile("cp.async.cg.shared.global [%0], [%1], 16;\n"
                 :: "r"(sa), "l"(gptr));
}
#define CP_COMMIT() asm volatile("cp.async.commit_group;\n" ::: "memory")
#define CP_WAIT1()  asm volatile("cp.async.wait_group 1;\n" ::: "memory")
#define CP_WAIT0()  asm volatile("cp.async.wait_group 0;\n" ::: "memory")

// ---------------- input split kernels ----------------------------------------------
__global__ __launch_bounds__(256) void split_x(const float* __restrict__ x)
{
    size_t i = ((size_t)blockIdx.x * 256 + threadIdx.x) * 8;
    float4 v0 = *(const float4*)(x + i);
    float4 v1 = *(const float4*)(x + i + 4);
    float vv[8] = {v0.x, v0.y, v0.z, v0.w, v1.x, v1.y, v1.z, v1.w};
    __half h[8], l[8];
#pragma unroll
    for (int j = 0; j < 8; j++) split_h(vv[j], h[j], l[j]);
    *(uint4*)(g_xh + i) = *(uint4*)h;
    *(uint4*)(g_xl + i) = *(uint4*)l;
}

// Transpose weight [768, N] -> [N, 768] single f16.  W=0: w_attn, W=1: w_proj
template <int W>
__global__ __launch_bounds__(256) void splitT_w(const float* __restrict__ w, int N)
{
    __shared__ float ts[32][33];
    const int tx = threadIdx.x & 31, ty = threadIdx.x >> 5;  // 32 x 8
    const int n0 = blockIdx.x * 32, k0 = blockIdx.y * 32;
#pragma unroll
    for (int i = 0; i < 4; i++) {
        int ky = ty + i * 8;
        ts[ky][tx] = w[(size_t)(k0 + ky) * N + n0 + tx];
    }
    __syncthreads();
    __half* th = (W == 0) ? g_wat : g_wpt;
#pragma unroll
    for (int i = 0; i < 4; i++) {
        int r = ty + i * 8;
        th[(size_t)(n0 + r) * DM + k0 + tx] = __float2half_rn(ts[tx][r]);
    }
}

// ---------------- 2-term f16 raw-mma GEMM, cp.async double-buffered -----------------
// C[M,N] = A*B^T + bias; A = hi/lo f16 (exact), B = single f16 (transposed [N,K]).
// Block tile 128x128xK32, 256 threads (8 warps, 4m x 2n, warp tile 32x64).
#define GM 128
#define GN 128
#define GKT 32
#define GLD 40
#define GCN 68
#define GST (3*GM*GLD)                 // halves per stage (AH+AL+BH) = 15360
#define GEMM_SMEM (2*GST*2 > GM*GCN*4 ? 2*GST*2 : GM*GCN*4)   // 61440 B

template <int MODE>
__global__ __launch_bounds__(256) void gemm_h(const float* __restrict__ bias,
                                              float* __restrict__ Cout, int N)
{
    constexpr int K = DM;
    const __half* __restrict__ Ah = (MODE == 1) ? g_xh : g_yh;
    const __half* __restrict__ Al = (MODE == 1) ? g_xl : g_yl;
    const __half* __restrict__ Bh = (MODE == 1) ? g_wat : g_wpt;

    extern __shared__ char gsm[];
    __half* ST = (__half*)gsm;
    float*  Cs = (float*)gsm;

    const int tid  = threadIdx.x;
    const int warp = tid >> 5, lane = tid & 31;
    const int g = lane >> 2, t = lane & 3;
    const int m0 = (warp & 3) * 32, wn = warp >> 2, n0 = wn * 64;
    const int bm = blockIdx.y * GM, bn = blockIdx.x * GN;

    const int ldr  = tid >> 2;            // 0..63
    const int ldc8 = (tid & 3) * 8;       // 0,8,16,24

    auto issue = [&](int k0, int s) {
        __half* AH = ST + s * GST;
        __half* AL = AH + GM * GLD;
        __half* BH = AL + GM * GLD;
#pragma unroll
        for (int i = 0; i < 2; i++) {
            int r = ldr + i * 64;
            cp16(AH + r * GLD + ldc8, Ah + (size_t)(bm + r) * K + k0 + ldc8);
            cp16(AL + r * GLD + ldc8, Al + (size_t)(bm + r) * K + k0 + ldc8);
            cp16(BH + r * GLD + ldc8, Bh + (size_t)(bn + r) * K + k0 + ldc8);
        }
    };

    float acc[2][8][4] = {};

    issue(0, 0);
    CP_COMMIT();

    const int nk = K / GKT;   // 24
    for (int kt = 0; kt < nk; kt++) {
        if (kt + 1 < nk) { issue((kt + 1) * GKT, (kt + 1) & 1); CP_COMMIT(); CP_WAIT1(); }
        else             { CP_WAIT0(); }
        __syncthreads();

        const __half* AH = ST + (kt & 1) * GST;
        const __half* AL = AH + GM * GLD;
        const __half* BH = AL + GM * GLD;

#pragma unroll
        for (int kc = 0; kc < 2; kc++) {
            const int dlo = kc * 16 + 2 * t;
            uint32_t aH[2][4], aL[2][4];
#pragma unroll
            for (int mi = 0; mi < 2; mi++) {
                int r0 = m0 + mi * 16 + g, r1 = r0 + 8;
                aH[mi][0] = lds32(AH + r0 * GLD + dlo);
                aH[mi][1] = lds32(AH + r1 * GLD + dlo);
                aH[mi][2] = lds32(AH + r0 * GLD + dlo + 8);
                aH[mi][3] = lds32(AH + r1 * GLD + dlo + 8);
                aL[mi][0] = lds32(AL + r0 * GLD + dlo);
                aL[mi][1] = lds32(AL + r1 * GLD + dlo);
                aL[mi][2] = lds32(AL + r0 * GLD + dlo + 8);
                aL[mi][3] = lds32(AL + r1 * GLD + dlo + 8);
            }
#pragma unroll
            for (int ni = 0; ni < 8; ni++) {
                int rn = n0 + ni * 8 + g;
                uint32_t b0 = lds32(BH + rn * GLD + dlo);
                uint32_t b1 = lds32(BH + rn * GLD + dlo + 8);
#pragma unroll
                for (int mi = 0; mi < 2; mi++) {
                    mma16816h(acc[mi][ni], aH[mi][0], aH[mi][1], aH[mi][2], aH[mi][3], b0, b1);
                    mma16816h(acc[mi][ni], aL[mi][0], aL[mi][1], aL[mi][2], aL[mi][3], b0, b1);
                }
            }
        }
        __syncthreads();
    }

    // Epilogue: two 64-col passes through Cs
#pragma unroll
    for (int pass = 0; pass < 2; pass++) {
        __syncthreads();
        if (wn == pass) {
#pragma unroll
            for (int mi = 0; mi < 2; mi++)
#pragma unroll
                for (int ni = 0; ni < 8; ni++) {
                    int r = m0 + mi * 16 + g, c = ni * 8 + 2 * t;
                    *(float2*)&Cs[r * GCN + c]       = make_float2(acc[mi][ni][0], acc[mi][ni][1]);
                    *(float2*)&Cs[(r + 8) * GCN + c] = make_float2(acc[mi][ni][2], acc[mi][ni][3]);
                }
        }
        __syncthreads();

        const int nwin = bn + pass * 64;
        if (MODE == 2) {
#pragma unroll
            for (int it = 0; it < 32; it++) {
                int idx = tid + it * 256;
                int r = idx >> 6;
                int n_loc = idx & 63;
                Cout[(size_t)(bm + r) * N + nwin + n_loc] = Cs[r * GCN + n_loc] + bias[nwin + n_loc];
            }
        } else {
            const int which = nwin / DM;
            const int hd    = nwin % DM;
            const int h     = hd / DH;
            const int b     = bm / TT;
            const int t0    = bm % TT;
            const int bh    = b * NH + h;

            if (which == 2) {
#pragma unroll
                for (int it = 0; it < 4; it++) {
                    int cid = tid + it * 256;
                    int d   = cid >> 4;
                    int tc  = (cid & 15) * 8;
                    float bval = bias[nwin + d];
                    __half hb[8];
#pragma unroll
                    for (int j = 0; j < 8; j++)
                        hb[j] = __float2half_rn(Cs[(tc + j) * GCN + d] + bval);
                    *(uint4*)(g_vt + ((size_t)bh * DH + d) * TT + t0 + tc) = *(uint4*)hb;
                }
            } else if (which == 1) {
#pragma unroll
                for (int it = 0; it < 4; it++) {
                    int cid = tid + it * 256;
                    int r   = cid >> 3;
                    int c8  = (cid & 7) * 8;
                    __half hb[8];
#pragma unroll
                    for (int j = 0; j < 8; j++)
                        hb[j] = __float2half_rn(Cs[r * GCN + c8 + j] + bias[nwin + c8 + j]);
                    *(uint4*)(g_k + ((size_t)bh * TT + t0 + r) * DH + c8) = *(uint4*)hb;
                }
            } else {
#pragma unroll
                for (int it = 0; it < 4; it++) {
                    int cid = tid + it * 256;
                    int r   = cid >> 3;
                    int c8  = (cid & 7) * 8;
                    __half hb[8], lb[8];
#pragma unroll
                    for (int j = 0; j < 8; j++) {
                        float v = (Cs[r * GCN + c8 + j] + bias[nwin + c8 + j]) * 0.125f;
                        split_h(v, hb[j], lb[j]);
                    }
                    size_t dst = ((size_t)bh * TT + t0 + r) * DH + c8;
                    *(uint4*)(g_qh + dst) = *(uint4*)hb;
                    *(uint4*)(g_ql + dst) = *(uint4*)lb;
                }
            }
        }
    }
}

// ---------------- Register-resident flash attention, cp.async K/V pipeline ---------
#define LOG2E 1.4426950408889634f
#define LDSB 72
// smem: QH, QL (resident) + 2 stages of (KH, VT)
#define AST (2*64*LDSB)                     // halves per stage = 9216
#define ATT_SMEM ((2*64*LDSB + 2*AST) * 2)  // 55296 B

__device__ __forceinline__ float fexp2(float t)   // t <= 0; returns 2^t
{
    t = fmaxf(t, -126.f);
    float fl = floorf(t);
    float x = (t - fl) * 0.69314718056f;
    float p = 1.f + x*(1.f + x*(0.5f + x*(0.16666667f + x*(0.041666667f
              + x*(0.0083333333f + x*0.0013888889f)))));
    return __int_as_float(__float_as_int(p) + ((int)fl << 23));
}

__global__ __launch_bounds__(128) void attn_reg()
{
    extern __shared__ __half smb[];
    __half* QH = smb;
    __half* QL = QH + 64*LDSB;
    __half* S0 = QL + 64*LDSB;     // stage base

    const int bh   = blockIdx.y;
    const int qt   = gridDim.x - 1 - blockIdx.x;  // heavy first
    const int tid  = threadIdx.x;
    const int warp = tid >> 5;
    const int lane = tid & 31;
    const int g    = lane >> 2;
    const int t    = lane & 3;
    const int q0   = qt * 64;

    const __half* gqh = g_qh + (size_t)bh * TT * DH;
    const __half* gql = g_ql + (size_t)bh * TT * DH;
    const __half* gk  = g_k  + (size_t)bh * TT * DH;
    const __half* gv  = g_vt + (size_t)bh * DH * TT;

    auto issue_kv = [&](int kt, int s) {
        __half* KH = S0 + s * AST;
        __half* VT = KH + 64 * LDSB;
#pragma unroll
        for (int it = 0; it < 4; it++) {
            int cid = tid + it * 128;
            int r   = cid >> 3;
            int c8  = (cid & 7) * 8;
            cp16(KH + r * LDSB + c8, gk + (size_t)(kt*64 + r) * DH + c8);
            cp16(VT + r * LDSB + c8, gv + (size_t)r * TT + kt*64 + c8);
        }
    };

    issue_kv(0, 0);
    CP_COMMIT();

#pragma unroll
    for (int it = 0; it < 4; it++) {
        int cid = tid + it * 128;
        int r   = cid >> 3;
        int c8  = (cid & 7) * 8;
        *(uint4*)(QH + r * LDSB + c8) = *(const uint4*)(gqh + (size_t)(q0 + r) * DH + c8);
        *(uint4*)(QL + r * LDSB + c8) = *(const uint4*)(gql + (size_t)(q0 + r) * DH + c8);
    }
    __syncthreads();

    // Hoist Q fragments into registers (block-invariant across kt)
    uint32_t qfh[4][4], qfl[4][4];
    {
        const int qrow = warp * 16 + g;
#pragma unroll
        for (int kc = 0; kc < 4; kc++) {
            const int dlo = kc * 16 + 2 * t;
            qfh[kc][0] = lds32(QH + qrow * LDSB + dlo);
            qfh[kc][1] = lds32(QH + (qrow + 8) * LDSB + dlo);
            qfh[kc][2] = lds32(QH + qrow * LDSB + dlo + 8);
            qfh[kc][3] = lds32(QH + (qrow + 8) * LDSB + dlo + 8);
            qfl[kc][0] = lds32(QL + qrow * LDSB + dlo);
            qfl[kc][1] = lds32(QL + (qrow + 8) * LDSB + dlo);
            qfl[kc][2] = lds32(QL + qrow * LDSB + dlo + 8);
            qfl[kc][3] = lds32(QL + (qrow + 8) * LDSB + dlo + 8);
        }
    }

    float o[8][4];
#pragma unroll
    for (int nt = 0; nt < 8; nt++)
#pragma unroll
        for (int e = 0; e < 4; e++) o[nt][e] = 0.f;
    float m0 = -1e30f, m1 = -1e30f, l0 = 0.f, l1 = 0.f;

    const int rowg  = q0 + warp * 16 + g;
    const int rowg8 = rowg + 8;

    for (int kt = 0; kt <= qt; kt++) {
        if (kt + 1 <= qt) { issue_kv(kt + 1, (kt + 1) & 1); CP_COMMIT(); CP_WAIT1(); }
        else              { CP_WAIT0(); }
        __syncthreads();

        const __half* KH = S0 + (kt & 1) * AST;
        const __half* VT = KH + 64 * LDSB;

        // ---- S = Q K^T ----
        float s[8][4];
#pragma unroll
        for (int nt = 0; nt < 8; nt++)
#pragma unroll
            for (int e = 0; e < 4; e++) s[nt][e] = 0.f;

#pragma unroll
        for (int kc = 0; kc < 4; kc++) {
            const int dlo = kc * 16 + 2 * t;
#pragma unroll
            for (int nt = 0; nt < 8; nt++) {
                const int krow = nt * 8 + g;
                uint32_t b0 = lds32(KH + krow * LDSB + dlo);
                uint32_t b1 = lds32(KH + krow * LDSB + dlo + 8);
                mma16816h(s[nt], qfh[kc][0], qfh[kc][1], qfh[kc][2], qfh[kc][3], b0, b1);
                mma16816h(s[nt], qfl[kc][0], qfl[kc][1], qfl[kc][2], qfl[kc][3], b0, b1);
            }
        }

        // ---- causal mask on the diagonal tile ----
        if (kt == qt) {
#pragma unroll
            for (int nt = 0; nt < 8; nt++) {
                int c0 = kt * 64 + nt * 8 + 2 * t;
                if (c0     > rowg)  s[nt][0] = -1e30f;
                if (c0 + 1 > rowg)  s[nt][1] = -1e30f;
                if (c0     > rowg8) s[nt][2] = -1e30f;
                if (c0 + 1 > rowg8) s[nt][3] = -1e30f;
            }
        }

        // ---- online softmax ----
        float tmax0 = -1e30f, tmax1 = -1e30f;
#pragma unroll
        for (int nt = 0; nt < 8; nt++) {
            tmax0 = fmaxf(tmax0, fmaxf(s[nt][0], s[nt][1]));
            tmax1 = fmaxf(tmax1, fmaxf(s[nt][2], s[nt][3]));
        }
        tmax0 = fmaxf(tmax0, __shfl_xor_sync(0xffffffff, tmax0, 1));
        tmax0 = fmaxf(tmax0, __shfl_xor_sync(0xffffffff, tmax0, 2));
        tmax1 = fmaxf(tmax1, __shfl_xor_sync(0xffffffff, tmax1, 1));
        tmax1 = fmaxf(tmax1, __shfl_xor_sync(0xffffffff, tmax1, 2));

        float mnew0 = fmaxf(m0, tmax0);
        float mnew1 = fmaxf(m1, tmax1);
        float f0 = fexp2((m0 - mnew0) * LOG2E);
        float f1 = fexp2((m1 - mnew1) * LOG2E);

        uint32_t pah[4][4], pal[4][4];
        float ls0 = 0.f, ls1 = 0.f;
#pragma unroll
        for (int kc = 0; kc < 4; kc++) {
            float p00 = fexp2((s[2*kc][0]   - mnew0) * LOG2E);
            float p01 = fexp2((s[2*kc][1]   - mnew0) * LOG2E);
            float p02 = fexp2((s[2*kc][2]   - mnew1) * LOG2E);
            float p03 = fexp2((s[2*kc][3]   - mnew1) * LOG2E);
            float p10 = fexp2((s[2*kc+1][0] - mnew0) * LOG2E);
            float p11 = fexp2((s[2*kc+1][1] - mnew0) * LOG2E);
            float p12 = fexp2((s[2*kc+1][2] - mnew1) * LOG2E);
            float p13 = fexp2((s[2*kc+1][3] - mnew1) * LOG2E);
            packsplit_h(p00, p01, pah[kc][0], pal[kc][0]);
            packsplit_h(p02, p03, pah[kc][1], pal[kc][1]);
            packsplit_h(p10, p11, pah[kc][2], pal[kc][2]);
            packsplit_h(p12, p13, pah[kc][3], pal[kc][3]);
            ls0 += (p00 + p01) + (p10 + p11);
            ls1 += (p02 + p03) + (p12 + p13);
        }
        ls0 += __shfl_xor_sync(0xffffffff, ls0, 1);
        ls0 += __shfl_xor_sync(0xffffffff, ls0, 2);
        ls1 += __shfl_xor_sync(0xffffffff, ls1, 1);
        ls1 += __shfl_xor_sync(0xffffffff, ls1, 2);

        l0 = l0 * f0 + ls0;  m0 = mnew0;
        l1 = l1 * f1 + ls1;  m1 = mnew1;

#pragma unroll
        for (int nt = 0; nt < 8; nt++) {
            o[nt][0] *= f0; o[nt][1] *= f0;
            o[nt][2] *= f1; o[nt][3] *= f1;
        }

        // ---- O += P * V (P exact hi/lo, V single f16) ----
#pragma unroll
        for (int kc = 0; kc < 4; kc++) {
            const int klo = kc * 16 + 2 * t;
#pragma unroll
            for (int nt = 0; nt < 8; nt++) {
                const int drow = nt * 8 + g;
                uint32_t v0 = lds32(VT + drow * LDSB + klo);
                uint32_t v1 = lds32(VT + drow * LDSB + klo + 8);
                mma16816h(o[nt], pah[kc][0], pah[kc][1], pah[kc][2], pah[kc][3], v0, v1);
                mma16816h(o[nt], pal[kc][0], pal[kc][1], pal[kc][2], pal[kc][3], v0, v1);
            }
        }
        __syncthreads();
    }

    // ---- epilogue: normalize, split f16 hi/lo, write g_yh/g_yl ----
    {
        float inv0 = 1.0f / l0;
        float inv1 = 1.0f / l1;
        int b = bh / NH, h = bh % NH;
        size_t off0 = ((size_t)(b * TT + rowg))  * DM + h * DH;
        size_t off1 = ((size_t)(b * TT + rowg8)) * DM + h * DH;
#pragma unroll
        for (int nt = 0; nt < 8; nt++) {
            int d = nt * 8 + 2 * t;
            uint32_t hi, lo;
            packsplit_h(o[nt][0] * inv0, o[nt][1] * inv0, hi, lo);
            *(uint32_t*)(g_yh + off0 + d) = hi;
            *(uint32_t*)(g_yl + off0 + d) = lo;
            packsplit_h(o[nt][2] * inv1, o[nt][3] * inv1, hi, lo);
            *(uint32_t*)(g_yh + off1 + d) = hi;
            *(uint32_t*)(g_yl + off1 + d) = lo;
        }
    }
}

// ---------------- launch -----------------------------------------------------------
extern "C" void kernel_launch(void* const* d_in, const int* in_sizes, int n_in,
                              void* d_out, int out_size)
{
    const float *x = nullptr, *wa = nullptr, *ba = nullptr, *wp = nullptr, *bp = nullptr;
    for (int divi = 0; divi < 2; divi++) {
        long long div = (divi == 0) ? 1 : 4;
        const float *tx=nullptr,*twa=nullptr,*tba=nullptr,*twp=nullptr,*tbp=nullptr;
        for (int i = 0; i < n_in; i++) {
            long long s = (long long)in_sizes[i] / div;
            if      (s == 3145728) tx  = (const float*)d_in[i];
            else if (s == 1769472) twa = (const float*)d_in[i];
            else if (s == 589824)  twp = (const float*)d_in[i];
            else if (s == 2304)    tba = (const float*)d_in[i];
            else if (s == 768)     tbp = (const float*)d_in[i];
        }
        if (tx && twa && tba && twp && tbp) { x=tx; wa=twa; ba=tba; wp=twp; bp=tbp; break; }
    }
    if (!(x && wa && ba && wp && bp)) return;

    float* out = (float*)d_out;

    cudaFuncSetAttribute(gemm_h<1>, cudaFuncAttributeMaxDynamicSharedMemorySize, GEMM_SMEM);
    cudaFuncSetAttribute(gemm_h<2>, cudaFuncAttributeMaxDynamicSharedMemorySize, GEMM_SMEM);
    cudaFuncSetAttribute(attn_reg,  cudaFuncAttributeMaxDynamicSharedMemorySize, ATT_SMEM);

    // 0) split x to f16 hi/lo; transpose weights to single f16
    split_x<<<MROWS * DM / (256 * 8), 256>>>(x);
    {
        dim3 gw(NQKV / 32, DM / 32);   // (72, 24)
        splitT_w<0><<<gw, 256>>>(wa, NQKV);
        dim3 gp(DM / 32, DM / 32);     // (24, 24)
        splitT_w<1><<<gp, 256>>>(wp, DM);
    }
    // 1) QKV projection (2-term f16, pipelined) -> q hi/lo, k f16, v f16 transposed
    {
        dim3 grid(NQKV / GN, MROWS / GM);   // (18, 32)
        gemm_h<1><<<grid, 256, GEMM_SMEM>>>(ba, nullptr, NQKV);
    }
    // 2) causal attention (pipelined K/V) -> g_yh/g_yl
    {
        dim3 grid(TT / 64, BB * NH);        // (32, 24)
        attn_reg<<<grid, 128, ATT_SMEM>>>();
    }
    // 3) output projection (2-term f16, pipelined)
    {
        dim3 grid(DM / GN, MROWS / GM);     // (6, 32)
        gemm_h<2><<<grid, 256, GEMM_SMEM>>>(bp, out, DM);
    }
}